// round 1
// baseline (speedup 1.0000x reference)
#include <cuda_runtime.h>

#define Bn  8
#define Cc  512
#define Ss  1024
#define NHh 8
#define HDd 64
#define M3  1536
#define EPSn 1e-5f

// ---------------- scratch (device globals: allocation-free) ----------------
__device__ float g_qkv[(size_t)Bn * M3 * Ss];            // [b][1536][1024]   50 MB
__device__ float g_attn[(size_t)Bn * NHh * Ss * Ss];     // [b*nh][1024][1024] 268 MB
__device__ float g_ao[(size_t)Bn * Cc * Ss];             // attn out, channel = d*8+n
__device__ float g_y[(size_t)Bn * Cc * Ss];              // proj out (pre-norm)
__device__ float g_stats[32];                            // [0:8)mean1 [8:16)rstd1 [16:24)mean2 [24:32)rstd2

// ---------------- per-batch mean / rstd over C*S elements ----------------
__global__ __launch_bounds__(256) void stats_kernel(const float* __restrict__ src, int off) {
    const int b = blockIdx.x;
    const float4* p = (const float4*)(src + (size_t)b * Cc * Ss);
    const int n4 = Cc * Ss / 4;
    float4 s = make_float4(0.f, 0.f, 0.f, 0.f);
    float4 s2 = make_float4(0.f, 0.f, 0.f, 0.f);
    for (int i = threadIdx.x; i < n4; i += 256) {
        float4 v = p[i];
        s.x += v.x; s.y += v.y; s.z += v.z; s.w += v.w;
        s2.x = fmaf(v.x, v.x, s2.x);
        s2.y = fmaf(v.y, v.y, s2.y);
        s2.z = fmaf(v.z, v.z, s2.z);
        s2.w = fmaf(v.w, v.w, s2.w);
    }
    float sum = (s.x + s.y) + (s.z + s.w);
    float sq  = (s2.x + s2.y) + (s2.z + s2.w);
    __shared__ float sh[256], sh2[256];
    sh[threadIdx.x] = sum; sh2[threadIdx.x] = sq;
    __syncthreads();
    for (int st = 128; st > 0; st >>= 1) {
        if (threadIdx.x < st) {
            sh[threadIdx.x]  += sh[threadIdx.x + st];
            sh2[threadIdx.x] += sh2[threadIdx.x + st];
        }
        __syncthreads();
    }
    if (threadIdx.x == 0) {
        const float N = (float)(Cc * Ss);
        float mean = sh[0] / N;
        float var  = sh2[0] / N - mean * mean;
        g_stats[off + b]     = mean;
        g_stats[off + 8 + b] = rsqrtf(var + EPSn);
    }
}

// ---------------- 128x128x8 SGEMM: C[b][M][S] = A[M,512] * B[b][512][S] + bias ----
// NORM=true: B element is normalized on load (groupnorm folded as scale/shift).
template<bool NORM>
__global__ __launch_bounds__(256) void gemm128(
    const float* __restrict__ A, const float* __restrict__ Bsrc,
    const float* __restrict__ bias, float* __restrict__ Cdst,
    const float* __restrict__ nw, const float* __restrict__ nb)
{
    const int b  = blockIdx.z;
    const int m0 = blockIdx.y * 128;
    const int n0 = blockIdx.x * 128;
    const int M  = gridDim.y * 128;
    const float* Bp = Bsrc + (size_t)b * Cc * Ss;
    float* Cp = Cdst + (size_t)b * M * Ss;

    float mean = 0.f, rstd = 1.f;
    if constexpr (NORM) { mean = g_stats[b]; rstd = g_stats[8 + b]; }

    __shared__ float As[8][128];
    __shared__ float Bs[8][128];

    const int t  = threadIdx.x;
    const int tx = t & 15, ty = t >> 4;
    const int am = t >> 1, ak = (t & 1) * 4;       // A tile: 128 rows x 8 k
    const int bk = t >> 5, bq = (t & 31) * 4;      // B tile: 8 k x 128 cols

    float acc[8][8] = {};

    float4 a4 = *(const float4*)(A + (size_t)(m0 + am) * Cc + ak);
    float4 b4;
    {
        const int c = bk;
        b4 = *(const float4*)(Bp + (size_t)c * Ss + n0 + bq);
        if constexpr (NORM) {
            float sc = rstd * nw[c];
            float sv = nb[c] - mean * sc;
            b4.x = fmaf(b4.x, sc, sv); b4.y = fmaf(b4.y, sc, sv);
            b4.z = fmaf(b4.z, sc, sv); b4.w = fmaf(b4.w, sc, sv);
        }
    }

    for (int k0 = 0; k0 < Cc; k0 += 8) {
        __syncthreads();
        As[ak + 0][am] = a4.x; As[ak + 1][am] = a4.y;
        As[ak + 2][am] = a4.z; As[ak + 3][am] = a4.w;
        *(float4*)&Bs[bk][bq] = b4;
        __syncthreads();

        if (k0 + 8 < Cc) {
            a4 = *(const float4*)(A + (size_t)(m0 + am) * Cc + (k0 + 8 + ak));
            const int c = k0 + 8 + bk;
            b4 = *(const float4*)(Bp + (size_t)c * Ss + n0 + bq);
            if constexpr (NORM) {
                float sc = rstd * nw[c];
                float sv = nb[c] - mean * sc;
                b4.x = fmaf(b4.x, sc, sv); b4.y = fmaf(b4.y, sc, sv);
                b4.z = fmaf(b4.z, sc, sv); b4.w = fmaf(b4.w, sc, sv);
            }
        }

        #pragma unroll
        for (int kk = 0; kk < 8; kk++) {
            float av[8], bv[8];
            *(float4*)&av[0] = *(const float4*)&As[kk][ty * 8];
            *(float4*)&av[4] = *(const float4*)&As[kk][ty * 8 + 4];
            *(float4*)&bv[0] = *(const float4*)&Bs[kk][tx * 8];
            *(float4*)&bv[4] = *(const float4*)&Bs[kk][tx * 8 + 4];
            #pragma unroll
            for (int i = 0; i < 8; i++)
                #pragma unroll
                for (int j = 0; j < 8; j++)
                    acc[i][j] = fmaf(av[i], bv[j], acc[i][j]);
        }
    }

    #pragma unroll
    for (int i = 0; i < 8; i++) {
        const int m = m0 + ty * 8 + i;
        const float bb = bias[m];
        float4 o0 = make_float4(acc[i][0] + bb, acc[i][1] + bb, acc[i][2] + bb, acc[i][3] + bb);
        float4 o1 = make_float4(acc[i][4] + bb, acc[i][5] + bb, acc[i][6] + bb, acc[i][7] + bb);
        *(float4*)(Cp + (size_t)m * Ss + n0 + tx * 8)     = o0;
        *(float4*)(Cp + (size_t)m * Ss + n0 + tx * 8 + 4) = o1;
    }
}

// ---------------- QK^T: S[i,j] = scale * sum_d Q[d,i] K[d,j], K-dim = 64 ---------
__global__ __launch_bounds__(256) void qk128() {
    const int bn = blockIdx.z, b = bn >> 3, n = bn & 7;
    const int i0 = blockIdx.y * 128, j0 = blockIdx.x * 128;
    const float* Q  = g_qkv + ((size_t)b * M3 + n * HDd) * Ss;        // rows d, cols s
    const float* Kp = g_qkv + ((size_t)b * M3 + Cc + n * HDd) * Ss;

    __shared__ float As[8][128];
    __shared__ float Bs[8][128];

    const int t  = threadIdx.x;
    const int tx = t & 15, ty = t >> 4;
    const int lk = t >> 5, lq = (t & 31) * 4;

    float acc[8][8] = {};

    float4 a4 = *(const float4*)(Q  + (size_t)lk * Ss + i0 + lq);
    float4 b4 = *(const float4*)(Kp + (size_t)lk * Ss + j0 + lq);

    for (int k0 = 0; k0 < HDd; k0 += 8) {
        __syncthreads();
        *(float4*)&As[lk][lq] = a4;
        *(float4*)&Bs[lk][lq] = b4;
        __syncthreads();

        if (k0 + 8 < HDd) {
            a4 = *(const float4*)(Q  + (size_t)(k0 + 8 + lk) * Ss + i0 + lq);
            b4 = *(const float4*)(Kp + (size_t)(k0 + 8 + lk) * Ss + j0 + lq);
        }

        #pragma unroll
        for (int kk = 0; kk < 8; kk++) {
            float av[8], bv[8];
            *(float4*)&av[0] = *(const float4*)&As[kk][ty * 8];
            *(float4*)&av[4] = *(const float4*)&As[kk][ty * 8 + 4];
            *(float4*)&bv[0] = *(const float4*)&Bs[kk][tx * 8];
            *(float4*)&bv[4] = *(const float4*)&Bs[kk][tx * 8 + 4];
            #pragma unroll
            for (int i = 0; i < 8; i++)
                #pragma unroll
                for (int j = 0; j < 8; j++)
                    acc[i][j] = fmaf(av[i], bv[j], acc[i][j]);
        }
    }

    float* P = g_attn + (size_t)bn * Ss * Ss;
    const float scale = 0.125f;   // HD^-0.5
    #pragma unroll
    for (int i = 0; i < 8; i++) {
        const int r = i0 + ty * 8 + i;
        float4 o0 = make_float4(acc[i][0] * scale, acc[i][1] * scale, acc[i][2] * scale, acc[i][3] * scale);
        float4 o1 = make_float4(acc[i][4] * scale, acc[i][5] * scale, acc[i][6] * scale, acc[i][7] * scale);
        *(float4*)(P + (size_t)r * Ss + j0 + tx * 8)     = o0;
        *(float4*)(P + (size_t)r * Ss + j0 + tx * 8 + 4) = o1;
    }
}

// ---------------- row softmax over 1024, in place ----------------
__global__ __launch_bounds__(128) void softmax128() {
    const size_t row = blockIdx.x;
    float* p = g_attn + row * Ss;
    const int t = threadIdx.x;
    float4 v0 = *(float4*)(p + t * 4);
    float4 v1 = *(float4*)(p + 512 + t * 4);

    float m = fmaxf(fmaxf(fmaxf(v0.x, v0.y), fmaxf(v0.z, v0.w)),
                    fmaxf(fmaxf(v1.x, v1.y), fmaxf(v1.z, v1.w)));
    #pragma unroll
    for (int o = 16; o; o >>= 1) m = fmaxf(m, __shfl_xor_sync(0xffffffffu, m, o));
    __shared__ float sred[4];
    if ((t & 31) == 0) sred[t >> 5] = m;
    __syncthreads();
    m = fmaxf(fmaxf(sred[0], sred[1]), fmaxf(sred[2], sred[3]));
    __syncthreads();

    v0.x = __expf(v0.x - m); v0.y = __expf(v0.y - m);
    v0.z = __expf(v0.z - m); v0.w = __expf(v0.w - m);
    v1.x = __expf(v1.x - m); v1.y = __expf(v1.y - m);
    v1.z = __expf(v1.z - m); v1.w = __expf(v1.w - m);

    float s = ((v0.x + v0.y) + (v0.z + v0.w)) + ((v1.x + v1.y) + (v1.z + v1.w));
    #pragma unroll
    for (int o = 16; o; o >>= 1) s += __shfl_xor_sync(0xffffffffu, s, o);
    if ((t & 31) == 0) sred[t >> 5] = s;
    __syncthreads();
    s = (sred[0] + sred[1]) + (sred[2] + sred[3]);
    const float inv = 1.0f / s;

    v0.x *= inv; v0.y *= inv; v0.z *= inv; v0.w *= inv;
    v1.x *= inv; v1.y *= inv; v1.z *= inv; v1.w *= inv;
    *(float4*)(p + t * 4)       = v0;
    *(float4*)(p + 512 + t * 4) = v1;
}

// ---------------- attn @ V : O[i,d] = sum_j P[i,j] * V[d,j]; store AO[d*8+n][i] ----
__global__ __launch_bounds__(128) void av128() {
    const int bn = blockIdx.y, b = bn >> 3, n = bn & 7;
    const int i0 = blockIdx.x * 128;
    const float* P = g_attn + (size_t)bn * Ss * Ss;
    const float* V = g_qkv + ((size_t)b * M3 + 2 * Cc + n * HDd) * Ss;  // [64 d][1024 j]
    float* AO = g_ao + (size_t)b * Cc * Ss;

    __shared__ float Ps[16][128];
    __shared__ float Vs[16][64];

    const int t  = threadIdx.x;
    const int tx = t & 15, ty = t >> 4;      // tx: i-group (16), ty: d-group (8)
    const int vd = t >> 1, vj = (t & 1) * 8;

    float acc[8][8] = {};                    // [dd][ii]

    const float* prow = P + (size_t)(i0 + t) * Ss;
    float4 p0 = *(const float4*)(prow + 0);
    float4 p1 = *(const float4*)(prow + 4);
    float4 p2 = *(const float4*)(prow + 8);
    float4 p3 = *(const float4*)(prow + 12);
    float4 q0 = *(const float4*)(V + (size_t)vd * Ss + vj);
    float4 q1 = *(const float4*)(V + (size_t)vd * Ss + vj + 4);

    for (int j0 = 0; j0 < Ss; j0 += 16) {
        __syncthreads();
        Ps[0][t]  = p0.x; Ps[1][t]  = p0.y; Ps[2][t]  = p0.z; Ps[3][t]  = p0.w;
        Ps[4][t]  = p1.x; Ps[5][t]  = p1.y; Ps[6][t]  = p1.z; Ps[7][t]  = p1.w;
        Ps[8][t]  = p2.x; Ps[9][t]  = p2.y; Ps[10][t] = p2.z; Ps[11][t] = p2.w;
        Ps[12][t] = p3.x; Ps[13][t] = p3.y; Ps[14][t] = p3.z; Ps[15][t] = p3.w;
        Vs[vj + 0][vd] = q0.x; Vs[vj + 1][vd] = q0.y;
        Vs[vj + 2][vd] = q0.z; Vs[vj + 3][vd] = q0.w;
        Vs[vj + 4][vd] = q1.x; Vs[vj + 5][vd] = q1.y;
        Vs[vj + 6][vd] = q1.z; Vs[vj + 7][vd] = q1.w;
        __syncthreads();

        if (j0 + 16 < Ss) {
            p0 = *(const float4*)(prow + j0 + 16);
            p1 = *(const float4*)(prow + j0 + 20);
            p2 = *(const float4*)(prow + j0 + 24);
            p3 = *(const float4*)(prow + j0 + 28);
            q0 = *(const float4*)(V + (size_t)vd * Ss + j0 + 16 + vj);
            q1 = *(const float4*)(V + (size_t)vd * Ss + j0 + 20 + vj);
        }

        #pragma unroll
        for (int kk = 0; kk < 16; kk++) {
            float av[8], bv[8];
            *(float4*)&av[0] = *(const float4*)&Ps[kk][tx * 8];
            *(float4*)&av[4] = *(const float4*)&Ps[kk][tx * 8 + 4];
            *(float4*)&bv[0] = *(const float4*)&Vs[kk][ty * 8];
            *(float4*)&bv[4] = *(const float4*)&Vs[kk][ty * 8 + 4];
            #pragma unroll
            for (int dd = 0; dd < 8; dd++)
                #pragma unroll
                for (int ii = 0; ii < 8; ii++)
                    acc[dd][ii] = fmaf(bv[dd], av[ii], acc[dd][ii]);
        }
    }

    #pragma unroll
    for (int dd = 0; dd < 8; dd++) {
        const int c = (ty * 8 + dd) * 8 + n;   // channel = d*NH + n  (reference transpose)
        float4 o0 = make_float4(acc[dd][0], acc[dd][1], acc[dd][2], acc[dd][3]);
        float4 o1 = make_float4(acc[dd][4], acc[dd][5], acc[dd][6], acc[dd][7]);
        *(float4*)(AO + (size_t)c * Ss + i0 + tx * 8)     = o0;
        *(float4*)(AO + (size_t)c * Ss + i0 + tx * 8 + 4) = o1;
    }
}

// ---------------- out = groupnorm(y) + residual ----------------
__global__ __launch_bounds__(256) void final_kernel(
    const float* __restrict__ x, const float* __restrict__ ow,
    const float* __restrict__ ob, float* __restrict__ out)
{
    const int idx = blockIdx.x * 256 + threadIdx.x;   // float4 index
    const int per_b = Cc * Ss / 4;
    const int b = idx / per_b;
    const int r = idx - b * per_b;
    const int c = r / (Ss / 4);
    const float mean = g_stats[16 + b], rstd = g_stats[24 + b];
    const float sc = rstd * ow[c];
    const float sv = ob[c] - mean * sc;
    float4 y  = *((const float4*)g_y + idx);
    float4 xv = *((const float4*)x + idx);
    float4 o;
    o.x = fmaf(y.x, sc, sv) + xv.x;
    o.y = fmaf(y.y, sc, sv) + xv.y;
    o.z = fmaf(y.z, sc, sv) + xv.z;
    o.w = fmaf(y.w, sc, sv) + xv.w;
    *((float4*)out + idx) = o;
}

// ---------------- launch ----------------
extern "C" void kernel_launch(void* const* d_in, const int* in_sizes, int n_in,
                              void* d_out, int out_size) {
    (void)in_sizes; (void)n_in; (void)out_size;
    const float* x      = (const float*)d_in[0];
    const float* norm_w = (const float*)d_in[1];
    const float* norm_b = (const float*)d_in[2];
    const float* qkv_w  = (const float*)d_in[3];
    const float* qkv_b  = (const float*)d_in[4];
    const float* proj_w = (const float*)d_in[5];
    const float* proj_b = (const float*)d_in[6];
    const float* onw    = (const float*)d_in[7];
    const float* onb    = (const float*)d_in[8];
    float* out = (float*)d_out;

    float *qkvp = nullptr, *aop = nullptr, *yp = nullptr;
    cudaGetSymbolAddress((void**)&qkvp, g_qkv);
    cudaGetSymbolAddress((void**)&aop,  g_ao);
    cudaGetSymbolAddress((void**)&yp,   g_y);

    // 1) norm stats of x
    stats_kernel<<<Bn, 256>>>(x, 0);
    // 2) QKV GEMM (norm folded into B-load)
    gemm128<true><<<dim3(Ss / 128, M3 / 128, Bn), 256>>>(qkv_w, x, qkv_b, qkvp, norm_w, norm_b);
    // 3) attention scores
    qk128<<<dim3(Ss / 128, Ss / 128, Bn * NHh), 256>>>();
    // 4) softmax
    softmax128<<<Bn * NHh * Ss, 128>>>();
    // 5) attn @ V (writes permuted channels)
    av128<<<dim3(Ss / 128, Bn * NHh), 128>>>();
    // 6) proj GEMM
    gemm128<false><<<dim3(Ss / 128, Cc / 128, Bn), 256>>>(proj_w, aop, proj_b, yp, nullptr, nullptr);
    // 7) out-norm stats, then norm + residual
    stats_kernel<<<Bn, 256>>>(yp, 16);
    final_kernel<<<(Bn * Cc * Ss / 4) / 256, 256>>>(x, onw, onb, out);
}

// round 3
// speedup vs baseline: 2.3312x; 2.3312x over previous
#include <cuda_runtime.h>
#include <cstdint>

#define Bn  8
#define Cc  512
#define Ss  1024
#define NHh 8
#define HDd 64
#define EPSn 1e-5f

// ---------------- scratch ----------------
__device__ float g_xn [(size_t)Bn * Cc * Ss];          // normalized+rounded x [b][c][s]
__device__ float g_w1 [(size_t)1536 * Cc];             // rounded qkv_w [ch][c]
__device__ float g_pwt[(size_t)Cc * Cc];               // rounded proj_w^T permuted: [k'=h*64+d][c]
__device__ float g_qt [(size_t)Bn * NHh * Ss * HDd];   // Q^T [b][h][s][d]
__device__ float g_k  [(size_t)Bn * NHh * HDd * Ss];   // K   [b][h][d][s]
__device__ float g_vt [(size_t)Bn * NHh * Ss * HDd];   // V^T [b][h][j][d]
__device__ float g_attn[(size_t)Bn * NHh * Ss * Ss];   // P   [bh][i][j]
__device__ float g_ao [(size_t)Bn * Ss * Cc];          // attn-out [b][s][k'=h*64+d]
__device__ float g_y  [(size_t)Bn * Ss * Cc];          // proj out [b][s][c]
__device__ float g_stats[32];

// ---------------- helpers ----------------
__device__ __forceinline__ uint32_t smem_u32(const void* p) {
    uint32_t a;
    asm("{ .reg .u64 t; cvta.to.shared.u64 t, %1; cvt.u32.u64 %0, t; }" : "=r"(a) : "l"(p));
    return a;
}
__device__ __forceinline__ float tf32r(float x) {
    uint32_t o;
    asm("cvt.rn.tf32.f32 %0, %1;" : "=r"(o) : "f"(x));
    return __uint_as_float(o);
}
#define CP_ASYNC16(dst, src) \
    asm volatile("cp.async.cg.shared.global [%0], [%1], 16;" :: "r"(dst), "l"(src))
#define CP_COMMIT() asm volatile("cp.async.commit_group;" ::: "memory")
#define CP_WAIT(n)  asm volatile("cp.async.wait_group %0;" :: "n"(n) : "memory")

__device__ __forceinline__ void mma8(float* c, const uint32_t* a, const uint32_t* b) {
    asm volatile(
        "mma.sync.aligned.m16n8k8.row.col.f32.tf32.tf32.f32 "
        "{%0,%1,%2,%3}, {%4,%5,%6,%7}, {%8,%9}, {%0,%1,%2,%3};"
        : "+f"(c[0]), "+f"(c[1]), "+f"(c[2]), "+f"(c[3])
        : "r"(a[0]), "r"(a[1]), "r"(a[2]), "r"(a[3]), "r"(b[0]), "r"(b[1]));
}

// ---------------- shared GEMM core ----------------
// C[128 x BN] = A[128 x ktot] (row-major, lda) * B[ktot x BN] ([k][n], ldb)
// 256 threads, BK=32, double-buffered cp.async smem, padded layouts:
//   As[m][36] (A pad 4), Bs[k][BN+8]
template<int BN, int WR, int WC>
struct Gemm {
    static constexpr int TM = 128 / WR / 16;
    static constexpr int TN = BN / WC / 8;
    static constexpr int BP = BN + 8;
    static constexpr int ASZ = 128 * 36;
    static constexpr int BSZ = 32 * BP;
    static constexpr int NB4 = BN / 32;          // B float4 per thread
    static constexpr int SMEM_BYTES = 2 * (ASZ + BSZ) * 4;

    __device__ static void issue(float* As, float* Bs,
                                 const float* __restrict__ A, int lda,
                                 const float* __restrict__ B, int ldb,
                                 int k0, int t) {
        #pragma unroll
        for (int i = 0; i < 4; i++) {
            const int id = t + 256 * i;
            const int row = id >> 3, c4 = id & 7;
            CP_ASYNC16(smem_u32(As + row * 36 + c4 * 4),
                       A + (size_t)row * lda + k0 + c4 * 4);
        }
        #pragma unroll
        for (int i = 0; i < NB4; i++) {
            const int id = t + 256 * i;
            const int row = id / (BN / 4), c4 = id % (BN / 4);
            CP_ASYNC16(smem_u32(Bs + row * BP + c4 * 4),
                       B + (size_t)(k0 + row) * ldb + c4 * 4);
        }
    }

    __device__ static void compute(const float* As, const float* Bs,
                                   float (&acc)[TM][TN][4]) {
        const int t = threadIdx.x, w = t >> 5, lane = t & 31;
        const int g = lane >> 2, tg = lane & 3;
        const int wm0 = (w / WC) * (128 / WR);
        const int wn0 = (w % WC) * (BN / WC);
        const uint32_t* Au = (const uint32_t*)As;
        const uint32_t* Bu = (const uint32_t*)Bs;
        #pragma unroll
        for (int kk = 0; kk < 4; kk++) {
            const int k8 = kk * 8;
            uint32_t a[TM][4], b[TN][2];
            #pragma unroll
            for (int mt = 0; mt < TM; mt++) {
                const uint32_t* ap = Au + (wm0 + mt * 16 + g) * 36 + k8 + tg;
                a[mt][0] = ap[0];
                a[mt][1] = ap[8 * 36];
                a[mt][2] = ap[4];
                a[mt][3] = ap[8 * 36 + 4];
            }
            #pragma unroll
            for (int nt = 0; nt < TN; nt++) {
                const uint32_t* bp = Bu + (k8 + tg) * BP + wn0 + nt * 8 + g;
                b[nt][0] = bp[0];
                b[nt][1] = bp[4 * BP];
            }
            #pragma unroll
            for (int mt = 0; mt < TM; mt++)
                #pragma unroll
                for (int nt = 0; nt < TN; nt++)
                    mma8(acc[mt][nt], a[mt], b[nt]);
        }
    }

    __device__ static void run(float* sm,
                               const float* __restrict__ A, int lda,
                               const float* __restrict__ B, int ldb,
                               int ktot, float (&acc)[TM][TN][4]) {
        float* As0 = sm;
        float* Bs0 = As0 + ASZ;
        float* As1 = Bs0 + BSZ;
        float* Bs1 = As1 + ASZ;
        const int t = threadIdx.x;
        const int NCH = ktot / 32;

        issue(As0, Bs0, A, lda, B, ldb, 0, t);
        CP_COMMIT();
        for (int c = 0; c < NCH; c++) {
            const int buf = c & 1;
            if (c + 1 < NCH) {
                issue(buf ? As0 : As1, buf ? Bs0 : Bs1, A, lda, B, ldb, (c + 1) * 32, t);
                CP_COMMIT();
                CP_WAIT(1);
            } else {
                CP_WAIT(0);
            }
            __syncthreads();
            compute(buf ? As1 : As0, buf ? Bs1 : Bs0, acc);
            __syncthreads();
        }
    }
};

using G128 = Gemm<128, 2, 4>;   // warp tile 64x32, TM=4 TN=4
using G64  = Gemm<64, 4, 2>;    // warp tile 32x32, TM=2 TN=4

// ---------------- prep kernels ----------------
__global__ __launch_bounds__(256) void stats_kernel(const float* __restrict__ src, int off) {
    const int b = blockIdx.x;
    const float4* p = (const float4*)(src + (size_t)b * Cc * Ss);
    const int n4 = Cc * Ss / 4;
    float s = 0.f, s2 = 0.f;
    for (int i = threadIdx.x; i < n4; i += 256) {
        float4 v = p[i];
        s += (v.x + v.y) + (v.z + v.w);
        s2 = fmaf(v.x, v.x, fmaf(v.y, v.y, fmaf(v.z, v.z, fmaf(v.w, v.w, s2))));
    }
    __shared__ float sh[256], sh2[256];
    sh[threadIdx.x] = s; sh2[threadIdx.x] = s2;
    __syncthreads();
    for (int st = 128; st > 0; st >>= 1) {
        if (threadIdx.x < st) { sh[threadIdx.x] += sh[threadIdx.x + st]; sh2[threadIdx.x] += sh2[threadIdx.x + st]; }
        __syncthreads();
    }
    if (threadIdx.x == 0) {
        const float N = (float)(Cc * Ss);
        float mean = sh[0] / N;
        float var  = sh2[0] / N - mean * mean;
        g_stats[off + b] = mean;
        g_stats[off + 8 + b] = rsqrtf(var + EPSn);
    }
}

__global__ __launch_bounds__(256) void norm_x(const float* __restrict__ x,
                                              const float* __restrict__ nw,
                                              const float* __restrict__ nb) {
    const int i4 = blockIdx.x * 256 + threadIdx.x;
    const int per_b = Cc * Ss / 4;
    const int b = i4 / per_b;
    const int r = i4 - b * per_b;
    const int c = r >> 8;
    const float mean = g_stats[b], rstd = g_stats[8 + b];
    const float sc = rstd * nw[c], sv = nb[c] - mean * sc;
    float4 v = ((const float4*)x)[i4];
    v.x = tf32r(fmaf(v.x, sc, sv));
    v.y = tf32r(fmaf(v.y, sc, sv));
    v.z = tf32r(fmaf(v.z, sc, sv));
    v.w = tf32r(fmaf(v.w, sc, sv));
    ((float4*)g_xn)[i4] = v;
}

__global__ __launch_bounds__(256) void prep_w1(const float* __restrict__ w) {
    const int i = blockIdx.x * 256 + threadIdx.x;
    g_w1[i] = tf32r(w[i]);
}
// pwt[k'][c] = proj_w[c][d*8+h], k' = h*64+d
__global__ __launch_bounds__(256) void prep_pwt(const float* __restrict__ w) {
    const int i = blockIdx.x * 256 + threadIdx.x;   // i = kp*512 + c
    const int kp = i >> 9, c = i & 511;
    const int h = kp >> 6, d = kp & 63;
    g_pwt[i] = tf32r(w[c * 512 + d * 8 + h]);
}

// ---------------- GEMM kernels ----------------
// QKV: D[m=ch(1536)][n=s(1024)] = w1 @ xn
__global__ __launch_bounds__(256, 2) void k_qkv(const float* __restrict__ qkvb) {
    extern __shared__ float dynsm[];
    const int b = blockIdx.z, m0 = blockIdx.y * 128, n0 = blockIdx.x * 128;
    float acc[4][4][4] = {};
    G128::run(dynsm, g_w1 + (size_t)m0 * Cc, Cc,
              g_xn + (size_t)b * Cc * Ss + n0, Ss, Cc, acc);

    const int t = threadIdx.x, w = t >> 5, lane = t & 31;
    const int g = lane >> 2, tg = lane & 3;
    const int wm0 = (w >> 2) * 64, wn0 = (w & 3) * 32;
    #pragma unroll
    for (int mt = 0; mt < 4; mt++) {
        #pragma unroll
        for (int half = 0; half < 2; half++) {
            const int ch = m0 + wm0 + mt * 16 + g + half * 8;
            const float bias = qkvb[ch];
            #pragma unroll
            for (int nt = 0; nt < 4; nt++) {
                const int s = n0 + wn0 + nt * 8 + 2 * tg;
                const float v0 = tf32r(acc[mt][nt][half * 2 + 0] + bias);
                const float v1 = tf32r(acc[mt][nt][half * 2 + 1] + bias);
                if (ch < 512) {            // Q -> qt[b][h][s][d]
                    const int h = ch >> 6, d = ch & 63;
                    float* dst = g_qt + (((size_t)b * 8 + h) * Ss + s) * 64 + d;
                    dst[0] = v0; dst[64] = v1;
                } else if (ch < 1024) {    // K -> k[b][h][d][s]
                    float* dst = g_k + ((size_t)b * 512 + (ch - 512)) * Ss + s;
                    dst[0] = v0; dst[1] = v1;
                } else {                   // V -> vt[b][h][j][d]
                    const int c2 = ch - 1024, h = c2 >> 6, d = c2 & 63;
                    float* dst = g_vt + (((size_t)b * 8 + h) * Ss + s) * 64 + d;
                    dst[0] = v0; dst[64] = v1;
                }
            }
        }
    }
}

// QK^T: P[i][j] = 0.125 * qt[i][:] . k[:][j]
__global__ __launch_bounds__(256, 2) void k_qk() {
    extern __shared__ float dynsm[];
    const int bh = blockIdx.z, m0 = blockIdx.y * 128, n0 = blockIdx.x * 128;
    float acc[4][4][4] = {};
    G128::run(dynsm, g_qt + ((size_t)bh * Ss + m0) * 64, 64,
              g_k + (size_t)bh * 64 * Ss + n0, Ss, 64, acc);

    const int t = threadIdx.x, w = t >> 5, lane = t & 31;
    const int g = lane >> 2, tg = lane & 3;
    const int wm0 = (w >> 2) * 64, wn0 = (w & 3) * 32;
    float* P = g_attn + ((size_t)bh << 20);
    #pragma unroll
    for (int mt = 0; mt < 4; mt++)
        #pragma unroll
        for (int half = 0; half < 2; half++) {
            const int i = m0 + wm0 + mt * 16 + g + half * 8;
            #pragma unroll
            for (int nt = 0; nt < 4; nt++) {
                const int j = n0 + wn0 + nt * 8 + 2 * tg;
                float2 v = make_float2(acc[mt][nt][half * 2] * 0.125f,
                                       acc[mt][nt][half * 2 + 1] * 0.125f);
                *(float2*)(P + (size_t)i * Ss + j) = v;
            }
        }
}

// softmax rows of P (tf32-rounded output)
__global__ __launch_bounds__(128) void softmax128() {
    const size_t row = blockIdx.x;
    float* p = g_attn + row * Ss;
    const int t = threadIdx.x;
    float4 v0 = *(float4*)(p + t * 4);
    float4 v1 = *(float4*)(p + 512 + t * 4);
    float m = fmaxf(fmaxf(fmaxf(v0.x, v0.y), fmaxf(v0.z, v0.w)),
                    fmaxf(fmaxf(v1.x, v1.y), fmaxf(v1.z, v1.w)));
    #pragma unroll
    for (int o = 16; o; o >>= 1) m = fmaxf(m, __shfl_xor_sync(0xffffffffu, m, o));
    __shared__ float sred[4];
    if ((t & 31) == 0) sred[t >> 5] = m;
    __syncthreads();
    m = fmaxf(fmaxf(sred[0], sred[1]), fmaxf(sred[2], sred[3]));
    __syncthreads();
    v0.x = __expf(v0.x - m); v0.y = __expf(v0.y - m);
    v0.z = __expf(v0.z - m); v0.w = __expf(v0.w - m);
    v1.x = __expf(v1.x - m); v1.y = __expf(v1.y - m);
    v1.z = __expf(v1.z - m); v1.w = __expf(v1.w - m);
    float s = ((v0.x + v0.y) + (v0.z + v0.w)) + ((v1.x + v1.y) + (v1.z + v1.w));
    #pragma unroll
    for (int o = 16; o; o >>= 1) s += __shfl_xor_sync(0xffffffffu, s, o);
    if ((t & 31) == 0) sred[t >> 5] = s;
    __syncthreads();
    s = (sred[0] + sred[1]) + (sred[2] + sred[3]);
    const float inv = 1.0f / s;
    v0.x = tf32r(v0.x * inv); v0.y = tf32r(v0.y * inv);
    v0.z = tf32r(v0.z * inv); v0.w = tf32r(v0.w * inv);
    v1.x = tf32r(v1.x * inv); v1.y = tf32r(v1.y * inv);
    v1.z = tf32r(v1.z * inv); v1.w = tf32r(v1.w * inv);
    *(float4*)(p + t * 4) = v0;
    *(float4*)(p + 512 + t * 4) = v1;
}

// P @ V^T: out[i][d] -> ao[b][i][h*64+d]
__global__ __launch_bounds__(256, 2) void k_av() {
    extern __shared__ float dynsm[];
    const int bh = blockIdx.z, m0 = blockIdx.y * 128;
    const int b = bh >> 3, h = bh & 7;
    float acc[2][4][4] = {};
    G64::run(dynsm, g_attn + ((size_t)bh << 20) + (size_t)m0 * Ss, Ss,
             g_vt + (size_t)bh * Ss * 64, 64, Ss, acc);

    const int t = threadIdx.x, w = t >> 5, lane = t & 31;
    const int g = lane >> 2, tg = lane & 3;
    const int wm0 = (w >> 1) * 32, wn0 = (w & 1) * 32;
    #pragma unroll
    for (int mt = 0; mt < 2; mt++)
        #pragma unroll
        for (int half = 0; half < 2; half++) {
            const int i = m0 + wm0 + mt * 16 + g + half * 8;
            #pragma unroll
            for (int nt = 0; nt < 4; nt++) {
                const int d = wn0 + nt * 8 + 2 * tg;
                float2 v = make_float2(tf32r(acc[mt][nt][half * 2]),
                                       tf32r(acc[mt][nt][half * 2 + 1]));
                *(float2*)(g_ao + ((size_t)b * Ss + i) * Cc + h * 64 + d) = v;
            }
        }
}

// proj: y[s][c] = ao[s][:] @ pwt[:][c] + bias
__global__ __launch_bounds__(256, 2) void k_proj(const float* __restrict__ projb) {
    extern __shared__ float dynsm[];
    const int b = blockIdx.z, m0 = blockIdx.y * 128, n0 = blockIdx.x * 128;
    float acc[4][4][4] = {};
    G128::run(dynsm, g_ao + ((size_t)b * Ss + m0) * Cc, Cc,
              g_pwt + n0, Cc, Cc, acc);

    const int t = threadIdx.x, w = t >> 5, lane = t & 31;
    const int g = lane >> 2, tg = lane & 3;
    const int wm0 = (w >> 2) * 64, wn0 = (w & 3) * 32;
    #pragma unroll
    for (int mt = 0; mt < 4; mt++)
        #pragma unroll
        for (int half = 0; half < 2; half++) {
            const int s = m0 + wm0 + mt * 16 + g + half * 8;
            #pragma unroll
            for (int nt = 0; nt < 4; nt++) {
                const int c = n0 + wn0 + nt * 8 + 2 * tg;
                float2 v = make_float2(acc[mt][nt][half * 2] + projb[c],
                                       acc[mt][nt][half * 2 + 1] + projb[c + 1]);
                *(float2*)(g_y + ((size_t)b * Ss + s) * Cc + c) = v;
            }
        }
}

// out[b][c][s] = gn(y[b][s][c]) + x[b][c][s]  (32x32 smem transpose)
__global__ __launch_bounds__(256) void final_kernel(
    const float* __restrict__ x, const float* __restrict__ ow,
    const float* __restrict__ ob, float* __restrict__ out)
{
    __shared__ float tl[32][33];
    const int b = blockIdx.z;
    const int s0 = blockIdx.x * 32, c0 = blockIdx.y * 32;
    const int tx = threadIdx.x, ty = threadIdx.y;
    const float mean = g_stats[16 + b], rstd = g_stats[24 + b];
    #pragma unroll
    for (int k = 0; k < 4; k++)
        tl[ty + 8 * k][tx] = g_y[((size_t)b * Ss + s0 + ty + 8 * k) * Cc + c0 + tx];
    __syncthreads();
    #pragma unroll
    for (int k = 0; k < 4; k++) {
        const int c = c0 + ty + 8 * k;
        const float sc = rstd * ow[c], sv = ob[c] - mean * sc;
        const size_t o = ((size_t)b * Cc + c) * Ss + s0 + tx;
        out[o] = fmaf(tl[tx][ty + 8 * k], sc, sv) + x[o];
    }
}

// ---------------- launch ----------------
extern "C" void kernel_launch(void* const* d_in, const int* in_sizes, int n_in,
                              void* d_out, int out_size) {
    (void)in_sizes; (void)n_in; (void)out_size;
    const float* x      = (const float*)d_in[0];
    const float* norm_w = (const float*)d_in[1];
    const float* norm_b = (const float*)d_in[2];
    const float* qkv_w  = (const float*)d_in[3];
    const float* qkv_b  = (const float*)d_in[4];
    const float* proj_w = (const float*)d_in[5];
    const float* proj_b = (const float*)d_in[6];
    const float* onw    = (const float*)d_in[7];
    const float* onb    = (const float*)d_in[8];
    float* out = (float*)d_out;

    const int SM128 = G128::SMEM_BYTES;   // 2*(4608+4352)*4 = 71680
    const int SM64  = G64::SMEM_BYTES;    // 2*(4608+2304)*4 = 55296
    cudaFuncSetAttribute(k_qkv,  cudaFuncAttributeMaxDynamicSharedMemorySize, SM128);
    cudaFuncSetAttribute(k_qk,   cudaFuncAttributeMaxDynamicSharedMemorySize, SM128);
    cudaFuncSetAttribute(k_av,   cudaFuncAttributeMaxDynamicSharedMemorySize, SM64);
    cudaFuncSetAttribute(k_proj, cudaFuncAttributeMaxDynamicSharedMemorySize, SM128);

    float* yp = nullptr;
    cudaGetSymbolAddress((void**)&yp, g_y);

    stats_kernel<<<Bn, 256>>>(x, 0);
    norm_x<<<(Bn * Cc * Ss / 4) / 256, 256>>>(x, norm_w, norm_b);
    prep_w1<<<(1536 * Cc) / 256, 256>>>(qkv_w);
    prep_pwt<<<(Cc * Cc) / 256, 256>>>(proj_w);

    k_qkv <<<dim3(8, 12, Bn), 256, SM128>>>(qkv_b);
    k_qk  <<<dim3(8, 8, Bn * NHh), 256, SM128>>>();
    softmax128<<<Bn * NHh * Ss, 128>>>();
    k_av  <<<dim3(1, 8, Bn * NHh), 256, SM64>>>();
    k_proj<<<dim3(4, 8, Bn), 256, SM128>>>(proj_b);

    stats_kernel<<<Bn, 256>>>(yp, 16);
    final_kernel<<<dim3(32, 16, Bn), dim3(32, 8)>>>(x, onw, onb, out);
}

// round 5
// speedup vs baseline: 2.9454x; 1.2635x over previous
#include <cuda_runtime.h>
#include <cstdint>

#define Bn  8
#define Cc  512
#define Ss  1024
#define NHh 8
#define HDd 64
#define EPSn 1e-5f

// ---------------- scratch ----------------
__device__ float g_xn [(size_t)Bn * Cc * Ss];          // normalized+rounded x [b][c][s]
__device__ float g_w1 [(size_t)1536 * Cc];             // rounded qkv_w [ch][c]
__device__ float g_pwt[(size_t)Cc * Cc];               // rounded proj_w^T permuted: [k'=h*64+d][c]
__device__ float g_qt [(size_t)Bn * NHh * Ss * HDd];   // Q^T [b][h][s][d]
__device__ float g_k  [(size_t)Bn * NHh * HDd * Ss];   // K   [b][h][d][s]
__device__ float g_vt [(size_t)Bn * NHh * Ss * HDd];   // V^T [b][h][j][d]
__device__ float g_ao [(size_t)Bn * Ss * Cc];          // attn-out [b][s][k'=h*64+d]
__device__ float g_y  [(size_t)Bn * Ss * Cc];          // proj out [b][s][c]
__device__ float g_stats[32];

// ---------------- helpers ----------------
__device__ __forceinline__ uint32_t smem_u32(const void* p) {
    uint32_t a;
    asm("{ .reg .u64 t; cvta.to.shared.u64 t, %1; cvt.u32.u64 %0, t; }" : "=r"(a) : "l"(p));
    return a;
}
__device__ __forceinline__ float tf32r(float x) {
    uint32_t o;
    asm("cvt.rn.tf32.f32 %0, %1;" : "=r"(o) : "f"(x));
    return __uint_as_float(o);
}
#define CP_ASYNC16(dst, src) \
    asm volatile("cp.async.cg.shared.global [%0], [%1], 16;" :: "r"(dst), "l"(src))
#define CP_COMMIT() asm volatile("cp.async.commit_group;" ::: "memory")
#define CP_WAIT(n)  asm volatile("cp.async.wait_group %0;" :: "n"(n) : "memory")

__device__ __forceinline__ void mma8(float* c, const uint32_t* a, const uint32_t* b) {
    asm volatile(
        "mma.sync.aligned.m16n8k8.row.col.f32.tf32.tf32.f32 "
        "{%0,%1,%2,%3}, {%4,%5,%6,%7}, {%8,%9}, {%0,%1,%2,%3};"
        : "+f"(c[0]), "+f"(c[1]), "+f"(c[2]), "+f"(c[3])
        : "r"(a[0]), "r"(a[1]), "r"(a[2]), "r"(a[3]), "r"(b[0]), "r"(b[1]));
}

// ---------------- shared GEMM core (dense GEMMs) ----------------
template<int BN, int WR, int WC>
struct Gemm {
    static constexpr int TM = 128 / WR / 16;
    static constexpr int TN = BN / WC / 8;
    static constexpr int BP = BN + 8;
    static constexpr int ASZ = 128 * 36;
    static constexpr int BSZ = 32 * BP;
    static constexpr int NB4 = BN / 32;
    static constexpr int SMEM_BYTES = 2 * (ASZ + BSZ) * 4;

    __device__ static void issue(float* As, float* Bs,
                                 const float* __restrict__ A, int lda,
                                 const float* __restrict__ B, int ldb,
                                 int k0, int t) {
        #pragma unroll
        for (int i = 0; i < 4; i++) {
            const int id = t + 256 * i;
            const int row = id >> 3, c4 = id & 7;
            CP_ASYNC16(smem_u32(As + row * 36 + c4 * 4),
                       A + (size_t)row * lda + k0 + c4 * 4);
        }
        #pragma unroll
        for (int i = 0; i < NB4; i++) {
            const int id = t + 256 * i;
            const int row = id / (BN / 4), c4 = id % (BN / 4);
            CP_ASYNC16(smem_u32(Bs + row * BP + c4 * 4),
                       B + (size_t)(k0 + row) * ldb + c4 * 4);
        }
    }

    __device__ static void compute(const float* As, const float* Bs,
                                   float (&acc)[TM][TN][4]) {
        const int t = threadIdx.x, w = t >> 5, lane = t & 31;
        const int g = lane >> 2, tg = lane & 3;
        const int wm0 = (w / WC) * (128 / WR);
        const int wn0 = (w % WC) * (BN / WC);
        const uint32_t* Au = (const uint32_t*)As;
        const uint32_t* Bu = (const uint32_t*)Bs;
        #pragma unroll
        for (int kk = 0; kk < 4; kk++) {
            const int k8 = kk * 8;
            uint32_t a[TM][4], b[TN][2];
            #pragma unroll
            for (int mt = 0; mt < TM; mt++) {
                const uint32_t* ap = Au + (wm0 + mt * 16 + g) * 36 + k8 + tg;
                a[mt][0] = ap[0];
                a[mt][1] = ap[8 * 36];
                a[mt][2] = ap[4];
                a[mt][3] = ap[8 * 36 + 4];
            }
            #pragma unroll
            for (int nt = 0; nt < TN; nt++) {
                const uint32_t* bp = Bu + (k8 + tg) * BP + wn0 + nt * 8 + g;
                b[nt][0] = bp[0];
                b[nt][1] = bp[4 * BP];
            }
            #pragma unroll
            for (int mt = 0; mt < TM; mt++)
                #pragma unroll
                for (int nt = 0; nt < TN; nt++)
                    mma8(acc[mt][nt], a[mt], b[nt]);
        }
    }

    __device__ static void run(float* sm,
                               const float* __restrict__ A, int lda,
                               const float* __restrict__ B, int ldb,
                               int ktot, float (&acc)[TM][TN][4]) {
        float* As0 = sm;
        float* Bs0 = As0 + ASZ;
        float* As1 = Bs0 + BSZ;
        float* Bs1 = As1 + ASZ;
        const int t = threadIdx.x;
        const int NCH = ktot / 32;

        issue(As0, Bs0, A, lda, B, ldb, 0, t);
        CP_COMMIT();
        for (int c = 0; c < NCH; c++) {
            const int buf = c & 1;
            if (c + 1 < NCH) {
                issue(buf ? As0 : As1, buf ? Bs0 : Bs1, A, lda, B, ldb, (c + 1) * 32, t);
                CP_COMMIT();
                CP_WAIT(1);
            } else {
                CP_WAIT(0);
            }
            __syncthreads();
            compute(buf ? As1 : As0, buf ? Bs1 : Bs0, acc);
            __syncthreads();
        }
    }
};

using G128 = Gemm<128, 2, 4>;

// ---------------- prep kernels ----------------
__global__ __launch_bounds__(256) void stats_kernel(const float* __restrict__ src, int off) {
    const int b = blockIdx.x;
    const float4* p = (const float4*)(src + (size_t)b * Cc * Ss);
    const int n4 = Cc * Ss / 4;
    float s = 0.f, s2 = 0.f;
    for (int i = threadIdx.x; i < n4; i += 256) {
        float4 v = p[i];
        s += (v.x + v.y) + (v.z + v.w);
        s2 = fmaf(v.x, v.x, fmaf(v.y, v.y, fmaf(v.z, v.z, fmaf(v.w, v.w, s2))));
    }
    __shared__ float sh[256], sh2[256];
    sh[threadIdx.x] = s; sh2[threadIdx.x] = s2;
    __syncthreads();
    for (int st = 128; st > 0; st >>= 1) {
        if (threadIdx.x < st) { sh[threadIdx.x] += sh[threadIdx.x + st]; sh2[threadIdx.x] += sh2[threadIdx.x + st]; }
        __syncthreads();
    }
    if (threadIdx.x == 0) {
        const float N = (float)(Cc * Ss);
        float mean = sh[0] / N;
        float var  = sh2[0] / N - mean * mean;
        g_stats[off + b] = mean;
        g_stats[off + 8 + b] = rsqrtf(var + EPSn);
    }
}

__global__ __launch_bounds__(256) void norm_x(const float* __restrict__ x,
                                              const float* __restrict__ nw,
                                              const float* __restrict__ nb) {
    const int i4 = blockIdx.x * 256 + threadIdx.x;
    const int per_b = Cc * Ss / 4;
    const int b = i4 / per_b;
    const int r = i4 - b * per_b;
    const int c = r >> 8;
    const float mean = g_stats[b], rstd = g_stats[8 + b];
    const float sc = rstd * nw[c], sv = nb[c] - mean * sc;
    float4 v = ((const float4*)x)[i4];
    v.x = tf32r(fmaf(v.x, sc, sv));
    v.y = tf32r(fmaf(v.y, sc, sv));
    v.z = tf32r(fmaf(v.z, sc, sv));
    v.w = tf32r(fmaf(v.w, sc, sv));
    ((float4*)g_xn)[i4] = v;
}

__global__ __launch_bounds__(256) void prep_w1(const float* __restrict__ w) {
    const int i = blockIdx.x * 256 + threadIdx.x;
    g_w1[i] = tf32r(w[i]);
}
__global__ __launch_bounds__(256) void prep_pwt(const float* __restrict__ w) {
    const int i = blockIdx.x * 256 + threadIdx.x;   // i = kp*512 + c
    const int kp = i >> 9, c = i & 511;
    const int h = kp >> 6, d = kp & 63;
    g_pwt[i] = tf32r(w[c * 512 + d * 8 + h]);
}

// ---------------- QKV GEMM ----------------
__global__ __launch_bounds__(256, 2) void k_qkv(const float* __restrict__ qkvb) {
    extern __shared__ float dynsm[];
    const int b = blockIdx.z, m0 = blockIdx.y * 128, n0 = blockIdx.x * 128;
    float acc[4][4][4] = {};
    G128::run(dynsm, g_w1 + (size_t)m0 * Cc, Cc,
              g_xn + (size_t)b * Cc * Ss + n0, Ss, Cc, acc);

    const int t = threadIdx.x, w = t >> 5, lane = t & 31;
    const int g = lane >> 2, tg = lane & 3;
    const int wm0 = (w >> 2) * 64, wn0 = (w & 3) * 32;
    #pragma unroll
    for (int mt = 0; mt < 4; mt++) {
        #pragma unroll
        for (int half = 0; half < 2; half++) {
            const int ch = m0 + wm0 + mt * 16 + g + half * 8;
            const float bias = qkvb[ch];
            #pragma unroll
            for (int nt = 0; nt < 4; nt++) {
                const int s = n0 + wn0 + nt * 8 + 2 * tg;
                const float v0 = tf32r(acc[mt][nt][half * 2 + 0] + bias);
                const float v1 = tf32r(acc[mt][nt][half * 2 + 1] + bias);
                if (ch < 512) {            // Q -> qt[b][h][s][d]
                    const int h = ch >> 6, d = ch & 63;
                    float* dst = g_qt + (((size_t)b * 8 + h) * Ss + s) * 64 + d;
                    dst[0] = v0; dst[64] = v1;
                } else if (ch < 1024) {    // K -> k[b][h][d][s]
                    float* dst = g_k + ((size_t)b * 512 + (ch - 512)) * Ss + s;
                    dst[0] = v0; dst[1] = v1;
                } else {                   // V -> vt[b][h][j][d]
                    const int c2 = ch - 1024, h = c2 >> 6, d = c2 & 63;
                    float* dst = g_vt + (((size_t)b * 8 + h) * Ss + s) * 64 + d;
                    dst[0] = v0; dst[64] = v1;
                }
            }
        }
    }
}

// ---------------- fused flash attention ----------------
// One CTA per (bh, 128-row i-tile). Warp w owns i-rows [16w, 16w+16).
// Smem: Ps [2][128][36] (P bounce / Q staging), Ks/Vs double-buffered [2][2][32][72].
__global__ __launch_bounds__(256, 2) void k_attn() {
    extern __shared__ float sm[];
    float* Ps = sm;            // 9216 floats
    float* Ks = sm + 9216;     // 2 bufs x 4608
    float* Vs = sm + 18432;    // 2 bufs x 4608
    const int bh = blockIdx.y, i0 = blockIdx.x * 128;
    const int b = bh >> 3, h = bh & 7;
    const int t = threadIdx.x, w = t >> 5, lane = t & 31;
    const int g = lane >> 2, tg = lane & 3;
    const int wr = w * 16;

    // stage Q tile -> Ps (A layout, chunked k32, pad 36)
    #pragma unroll
    for (int i = 0; i < 8; i++) {
        const int id = t + 256 * i;
        const int row = id >> 4, col = (id & 15) * 4;
        CP_ASYNC16(smem_u32(Ps + (col >> 5) * 4608 + row * 36 + (col & 31)),
                   g_qt + ((size_t)bh * Ss + i0 + row) * 64 + col);
    }
    CP_COMMIT();

    // K/V tile loader: K [d][j] rows d, V [j][d] rows j; B layout pad 72, chunked k32
    auto issue_kv = [&](int jt, int buf) {
        #pragma unroll
        for (int i = 0; i < 4; i++) {
            const int id = t + 256 * i;
            const int row = id >> 4, c4 = (id & 15) * 4;
            const uint32_t doff = buf * 4608 + (row >> 5) * 2304 + (row & 31) * 72 + c4;
            CP_ASYNC16(smem_u32(Ks + doff),
                       g_k + ((size_t)bh * 64 + row) * Ss + jt * 64 + c4);
            CP_ASYNC16(smem_u32(Vs + doff),
                       g_vt + ((size_t)bh * Ss + jt * 64 + row) * 64 + c4);
        }
    };
    issue_kv(0, 0);
    CP_COMMIT();

    CP_WAIT(1);          // Q staged
    __syncthreads();
    uint32_t qf[8][4];
    #pragma unroll
    for (int kf = 0; kf < 8; kf++) {
        const uint32_t* qp = (const uint32_t*)(Ps + (kf >> 2) * 4608 + (wr + g) * 36 + (kf & 3) * 8 + tg);
        qf[kf][0] = qp[0]; qf[kf][1] = qp[8 * 36];
        qf[kf][2] = qp[4]; qf[kf][3] = qp[8 * 36 + 4];
    }

    float o[8][4] = {};
    float m0 = -1e30f, m1 = -1e30f, l0 = 0.f, l1 = 0.f;

    for (int jt = 0; jt < 16; jt++) {
        const int buf = jt & 1;
        if (jt + 1 < 16) { issue_kv(jt + 1, buf ^ 1); CP_COMMIT(); CP_WAIT(1); }
        else             { CP_WAIT(0); }
        __syncthreads();   // K/V[buf] landed

        // ---- S = Q @ K^T (warp tile 16 x 64) ----
        float s[8][4] = {};
        const float* Kb = Ks + buf * 4608;
        #pragma unroll
        for (int kf = 0; kf < 8; kf++) {
            const uint32_t* bb = (const uint32_t*)(Kb + (kf >> 2) * 2304 + ((kf & 3) * 8 + tg) * 72 + g);
            #pragma unroll
            for (int nt = 0; nt < 8; nt++) {
                uint32_t bfr[2] = { bb[nt * 8], bb[4 * 72 + nt * 8] };
                mma8(s[nt], qf[kf], bfr);
            }
        }

        // ---- online softmax (rows g and g+8 of warp tile) ----
        float tm0 = -1e30f, tm1 = -1e30f;
        #pragma unroll
        for (int nt = 0; nt < 8; nt++) {
            s[nt][0] *= 0.125f; s[nt][1] *= 0.125f;
            s[nt][2] *= 0.125f; s[nt][3] *= 0.125f;
            tm0 = fmaxf(tm0, fmaxf(s[nt][0], s[nt][1]));
            tm1 = fmaxf(tm1, fmaxf(s[nt][2], s[nt][3]));
        }
        tm0 = fmaxf(tm0, __shfl_xor_sync(0xffffffffu, tm0, 1));
        tm0 = fmaxf(tm0, __shfl_xor_sync(0xffffffffu, tm0, 2));
        tm1 = fmaxf(tm1, __shfl_xor_sync(0xffffffffu, tm1, 1));
        tm1 = fmaxf(tm1, __shfl_xor_sync(0xffffffffu, tm1, 2));
        const float nm0 = fmaxf(m0, tm0), nm1 = fmaxf(m1, tm1);
        const float al0 = __expf(m0 - nm0), al1 = __expf(m1 - nm1);
        m0 = nm0; m1 = nm1;

        float ps0 = 0.f, ps1 = 0.f;
        #pragma unroll
        for (int nt = 0; nt < 8; nt++) {
            float p0 = __expf(s[nt][0] - m0), p1 = __expf(s[nt][1] - m0);
            float p2 = __expf(s[nt][2] - m1), p3 = __expf(s[nt][3] - m1);
            ps0 += p0 + p1; ps1 += p2 + p3;
            s[nt][0] = tf32r(p0); s[nt][1] = tf32r(p1);
            s[nt][2] = tf32r(p2); s[nt][3] = tf32r(p3);
        }
        ps0 += __shfl_xor_sync(0xffffffffu, ps0, 1);
        ps0 += __shfl_xor_sync(0xffffffffu, ps0, 2);
        ps1 += __shfl_xor_sync(0xffffffffu, ps1, 1);
        ps1 += __shfl_xor_sync(0xffffffffu, ps1, 2);
        l0 = l0 * al0 + ps0;
        l1 = l1 * al1 + ps1;
        #pragma unroll
        for (int nf = 0; nf < 8; nf++) {
            o[nf][0] *= al0; o[nf][1] *= al0;
            o[nf][2] *= al1; o[nf][3] *= al1;
        }

        // ---- bounce P through smem into A layout (warp-private rows) ----
        #pragma unroll
        for (int nt = 0; nt < 8; nt++) {
            float* pp = Ps + (nt >> 2) * 4608 + (wr + g) * 36 + (nt & 3) * 8 + 2 * tg;
            *(float2*)pp            = make_float2(s[nt][0], s[nt][1]);
            *(float2*)(pp + 8 * 36) = make_float2(s[nt][2], s[nt][3]);
        }
        __syncwarp();   // intra-warp fragment exchange only

        // ---- O += P @ V ----
        const float* Vb = Vs + buf * 4608;
        #pragma unroll
        for (int kf = 0; kf < 8; kf++) {
            const uint32_t* ap = (const uint32_t*)(Ps + (kf >> 2) * 4608 + (wr + g) * 36 + (kf & 3) * 8 + tg);
            uint32_t a[4] = { ap[0], ap[8 * 36], ap[4], ap[8 * 36 + 4] };
            const uint32_t* bb = (const uint32_t*)(Vb + (kf >> 2) * 2304 + ((kf & 3) * 8 + tg) * 72 + g);
            #pragma unroll
            for (int nf = 0; nf < 8; nf++) {
                uint32_t bfr[2] = { bb[nf * 8], bb[4 * 72 + nf * 8] };
                mma8(o[nf], a, bfr);
            }
        }

        // all warps done reading Ks/Vs[buf] before next iteration's cp.async
        // overwrites buf^1 (which is read two iterations apart) — WAR guard.
        __syncthreads();
    }

    // ---- epilogue: O /= l, write ao[b][i][h*64+d] ----
    const float inv0 = 1.0f / l0, inv1 = 1.0f / l1;
    float* dst = g_ao + ((size_t)b * Ss + i0 + wr + g) * Cc + h * 64 + 2 * tg;
    #pragma unroll
    for (int nf = 0; nf < 8; nf++) {
        *(float2*)(dst + nf * 8) =
            make_float2(tf32r(o[nf][0] * inv0), tf32r(o[nf][1] * inv0));
        *(float2*)(dst + 8 * Cc + nf * 8) =
            make_float2(tf32r(o[nf][2] * inv1), tf32r(o[nf][3] * inv1));
    }
}

// ---------------- proj GEMM ----------------
__global__ __launch_bounds__(256, 2) void k_proj(const float* __restrict__ projb) {
    extern __shared__ float dynsm[];
    const int b = blockIdx.z, m0 = blockIdx.y * 128, n0 = blockIdx.x * 128;
    float acc[4][4][4] = {};
    G128::run(dynsm, g_ao + ((size_t)b * Ss + m0) * Cc, Cc,
              g_pwt + n0, Cc, Cc, acc);

    const int t = threadIdx.x, w = t >> 5, lane = t & 31;
    const int g = lane >> 2, tg = lane & 3;
    const int wm0 = (w >> 2) * 64, wn0 = (w & 3) * 32;
    #pragma unroll
    for (int mt = 0; mt < 4; mt++)
        #pragma unroll
        for (int half = 0; half < 2; half++) {
            const int s = m0 + wm0 + mt * 16 + g + half * 8;
            #pragma unroll
            for (int nt = 0; nt < 4; nt++) {
                const int c = n0 + wn0 + nt * 8 + 2 * tg;
                float2 v = make_float2(acc[mt][nt][half * 2] + projb[c],
                                       acc[mt][nt][half * 2 + 1] + projb[c + 1]);
                *(float2*)(g_y + ((size_t)b * Ss + s) * Cc + c) = v;
            }
        }
}

// out[b][c][s] = gn(y[b][s][c]) + x[b][c][s]
__global__ __launch_bounds__(256) void final_kernel(
    const float* __restrict__ x, const float* __restrict__ ow,
    const float* __restrict__ ob, float* __restrict__ out)
{
    __shared__ float tl[32][33];
    const int b = blockIdx.z;
    const int s0 = blockIdx.x * 32, c0 = blockIdx.y * 32;
    const int tx = threadIdx.x, ty = threadIdx.y;
    const float mean = g_stats[16 + b], rstd = g_stats[24 + b];
    #pragma unroll
    for (int k = 0; k < 4; k++)
        tl[ty + 8 * k][tx] = g_y[((size_t)b * Ss + s0 + ty + 8 * k) * Cc + c0 + tx];
    __syncthreads();
    #pragma unroll
    for (int k = 0; k < 4; k++) {
        const int c = c0 + ty + 8 * k;
        const float sc = rstd * ow[c], sv = ob[c] - mean * sc;
        const size_t o = ((size_t)b * Cc + c) * Ss + s0 + tx;
        out[o] = fmaf(tl[tx][ty + 8 * k], sc, sv) + x[o];
    }
}

// ---------------- launch ----------------
extern "C" void kernel_launch(void* const* d_in, const int* in_sizes, int n_in,
                              void* d_out, int out_size) {
    (void)in_sizes; (void)n_in; (void)out_size;
    const float* x      = (const float*)d_in[0];
    const float* norm_w = (const float*)d_in[1];
    const float* norm_b = (const float*)d_in[2];
    const float* qkv_w  = (const float*)d_in[3];
    const float* qkv_b  = (const float*)d_in[4];
    const float* proj_w = (const float*)d_in[5];
    const float* proj_b = (const float*)d_in[6];
    const float* onw    = (const float*)d_in[7];
    const float* onb    = (const float*)d_in[8];
    float* out = (float*)d_out;

    const int SM128   = G128::SMEM_BYTES;      // 71680
    const int SM_ATTN = 27648 * 4;              // 110592
    cudaFuncSetAttribute(k_qkv,  cudaFuncAttributeMaxDynamicSharedMemorySize, SM128);
    cudaFuncSetAttribute(k_attn, cudaFuncAttributeMaxDynamicSharedMemorySize, SM_ATTN);
    cudaFuncSetAttribute(k_proj, cudaFuncAttributeMaxDynamicSharedMemorySize, SM128);

    float* yp = nullptr;
    cudaGetSymbolAddress((void**)&yp, g_y);

    stats_kernel<<<Bn, 256>>>(x, 0);
    norm_x<<<(Bn * Cc * Ss / 4) / 256, 256>>>(x, norm_w, norm_b);
    prep_w1<<<(1536 * Cc) / 256, 256>>>(qkv_w);
    prep_pwt<<<(Cc * Cc) / 256, 256>>>(proj_w);

    k_qkv <<<dim3(8, 12, Bn), 256, SM128>>>(qkv_b);
    k_attn<<<dim3(8, 64), 256, SM_ATTN>>>();
    k_proj<<<dim3(4, 8, Bn), 256, SM128>>>(proj_b);

    stats_kernel<<<Bn, 256>>>(yp, 16);
    final_kernel<<<dim3(32, 16, Bn), dim3(32, 8)>>>(x, onw, onb, out);
}

// round 6
// speedup vs baseline: 3.0979x; 1.0517x over previous
#include <cuda_runtime.h>
#include <cstdint>

#define Bn  8
#define Cc  512
#define Ss  1024
#define NHh 8
#define HDd 64
#define EPSn 1e-5f

// ---------------- scratch ----------------
__device__ float g_xn [(size_t)Bn * Cc * Ss];          // normalized+rounded x [b][c][s]
__device__ float g_w1 [(size_t)1536 * Cc];             // rounded qkv_w [ch][c]
__device__ float g_pwt[(size_t)Cc * Cc];               // rounded proj_w^T permuted: [k'=h*64+d][c]
__device__ float g_qt [(size_t)Bn * NHh * Ss * HDd];   // Q^T [b][h][s][d]
__device__ float g_k  [(size_t)Bn * NHh * HDd * Ss];   // K   [b][h][d][s]
__device__ float g_vt [(size_t)Bn * NHh * Ss * HDd];   // V^T [b][h][j][d]
__device__ float g_ao [(size_t)Bn * Ss * Cc];          // attn-out [b][s][k'=h*64+d]
__device__ float g_y  [(size_t)Bn * Ss * Cc];          // proj out [b][s][c]
__device__ float g_stats[32];

// ---------------- helpers ----------------
__device__ __forceinline__ uint32_t smem_u32(const void* p) {
    uint32_t a;
    asm("{ .reg .u64 t; cvta.to.shared.u64 t, %1; cvt.u32.u64 %0, t; }" : "=r"(a) : "l"(p));
    return a;
}
__device__ __forceinline__ float tf32r(float x) {
    uint32_t o;
    asm("cvt.rn.tf32.f32 %0, %1;" : "=r"(o) : "f"(x));
    return __uint_as_float(o);
}
#define CP_ASYNC16(dst, src) \
    asm volatile("cp.async.cg.shared.global [%0], [%1], 16;" :: "r"(dst), "l"(src))
#define CP_COMMIT() asm volatile("cp.async.commit_group;" ::: "memory")
#define CP_WAIT(n)  asm volatile("cp.async.wait_group %0;" :: "n"(n) : "memory")

__device__ __forceinline__ void mma8(float* c, const uint32_t* a, const uint32_t* b) {
    asm volatile(
        "mma.sync.aligned.m16n8k8.row.col.f32.tf32.tf32.f32 "
        "{%0,%1,%2,%3}, {%4,%5,%6,%7}, {%8,%9}, {%0,%1,%2,%3};"
        : "+f"(c[0]), "+f"(c[1]), "+f"(c[2]), "+f"(c[3])
        : "r"(a[0]), "r"(a[1]), "r"(a[2]), "r"(a[3]), "r"(b[0]), "r"(b[1]));
}

// ---------------- shared GEMM core (dense GEMMs) ----------------
template<int BN, int WR, int WC>
struct Gemm {
    static constexpr int TM = 128 / WR / 16;
    static constexpr int TN = BN / WC / 8;
    static constexpr int BP = BN + 8;
    static constexpr int ASZ = 128 * 36;
    static constexpr int BSZ = 32 * BP;
    static constexpr int NB4 = BN / 32;
    static constexpr int SMEM_BYTES = 2 * (ASZ + BSZ) * 4;

    __device__ static void issue(float* As, float* Bs,
                                 const float* __restrict__ A, int lda,
                                 const float* __restrict__ B, int ldb,
                                 int k0, int t) {
        #pragma unroll
        for (int i = 0; i < 4; i++) {
            const int id = t + 256 * i;
            const int row = id >> 3, c4 = id & 7;
            CP_ASYNC16(smem_u32(As + row * 36 + c4 * 4),
                       A + (size_t)row * lda + k0 + c4 * 4);
        }
        #pragma unroll
        for (int i = 0; i < NB4; i++) {
            const int id = t + 256 * i;
            const int row = id / (BN / 4), c4 = id % (BN / 4);
            CP_ASYNC16(smem_u32(Bs + row * BP + c4 * 4),
                       B + (size_t)(k0 + row) * ldb + c4 * 4);
        }
    }

    __device__ static void compute(const float* As, const float* Bs,
                                   float (&acc)[TM][TN][4]) {
        const int t = threadIdx.x, w = t >> 5, lane = t & 31;
        const int g = lane >> 2, tg = lane & 3;
        const int wm0 = (w / WC) * (128 / WR);
        const int wn0 = (w % WC) * (BN / WC);
        const uint32_t* Au = (const uint32_t*)As;
        const uint32_t* Bu = (const uint32_t*)Bs;
        #pragma unroll
        for (int kk = 0; kk < 4; kk++) {
            const int k8 = kk * 8;
            uint32_t a[TM][4], b[TN][2];
            #pragma unroll
            for (int mt = 0; mt < TM; mt++) {
                const uint32_t* ap = Au + (wm0 + mt * 16 + g) * 36 + k8 + tg;
                a[mt][0] = ap[0];
                a[mt][1] = ap[8 * 36];
                a[mt][2] = ap[4];
                a[mt][3] = ap[8 * 36 + 4];
            }
            #pragma unroll
            for (int nt = 0; nt < TN; nt++) {
                const uint32_t* bp = Bu + (k8 + tg) * BP + wn0 + nt * 8 + g;
                b[nt][0] = bp[0];
                b[nt][1] = bp[4 * BP];
            }
            #pragma unroll
            for (int mt = 0; mt < TM; mt++)
                #pragma unroll
                for (int nt = 0; nt < TN; nt++)
                    mma8(acc[mt][nt], a[mt], b[nt]);
        }
    }

    __device__ static void run(float* sm,
                               const float* __restrict__ A, int lda,
                               const float* __restrict__ B, int ldb,
                               int ktot, float (&acc)[TM][TN][4]) {
        float* As0 = sm;
        float* Bs0 = As0 + ASZ;
        float* As1 = Bs0 + BSZ;
        float* Bs1 = As1 + ASZ;
        const int t = threadIdx.x;
        const int NCH = ktot / 32;

        issue(As0, Bs0, A, lda, B, ldb, 0, t);
        CP_COMMIT();
        for (int c = 0; c < NCH; c++) {
            const int buf = c & 1;
            if (c + 1 < NCH) {
                issue(buf ? As0 : As1, buf ? Bs0 : Bs1, A, lda, B, ldb, (c + 1) * 32, t);
                CP_COMMIT();
                CP_WAIT(1);
            } else {
                CP_WAIT(0);
            }
            __syncthreads();
            compute(buf ? As1 : As0, buf ? Bs1 : Bs0, acc);
            __syncthreads();
        }
    }
};

using G128 = Gemm<128, 2, 4>;

// ---------------- prep kernels ----------------
__global__ __launch_bounds__(256) void stats_kernel(const float* __restrict__ src, int off) {
    const int b = blockIdx.x;
    const float4* p = (const float4*)(src + (size_t)b * Cc * Ss);
    const int n4 = Cc * Ss / 4;
    float s = 0.f, s2 = 0.f;
    for (int i = threadIdx.x; i < n4; i += 256) {
        float4 v = p[i];
        s += (v.x + v.y) + (v.z + v.w);
        s2 = fmaf(v.x, v.x, fmaf(v.y, v.y, fmaf(v.z, v.z, fmaf(v.w, v.w, s2))));
    }
    __shared__ float sh[256], sh2[256];
    sh[threadIdx.x] = s; sh2[threadIdx.x] = s2;
    __syncthreads();
    for (int st = 128; st > 0; st >>= 1) {
        if (threadIdx.x < st) { sh[threadIdx.x] += sh[threadIdx.x + st]; sh2[threadIdx.x] += sh2[threadIdx.x + st]; }
        __syncthreads();
    }
    if (threadIdx.x == 0) {
        const float N = (float)(Cc * Ss);
        float mean = sh[0] / N;
        float var  = sh2[0] / N - mean * mean;
        g_stats[off + b] = mean;
        g_stats[off + 8 + b] = rsqrtf(var + EPSn);
    }
}

__global__ __launch_bounds__(256) void norm_x(const float* __restrict__ x,
                                              const float* __restrict__ nw,
                                              const float* __restrict__ nb) {
    const int i4 = blockIdx.x * 256 + threadIdx.x;
    const int per_b = Cc * Ss / 4;
    const int b = i4 / per_b;
    const int r = i4 - b * per_b;
    const int c = r >> 8;
    const float mean = g_stats[b], rstd = g_stats[8 + b];
    const float sc = rstd * nw[c], sv = nb[c] - mean * sc;
    float4 v = ((const float4*)x)[i4];
    v.x = tf32r(fmaf(v.x, sc, sv));
    v.y = tf32r(fmaf(v.y, sc, sv));
    v.z = tf32r(fmaf(v.z, sc, sv));
    v.w = tf32r(fmaf(v.w, sc, sv));
    ((float4*)g_xn)[i4] = v;
}

// merged weight prep: [0, 1536*512) -> g_w1, rest -> g_pwt (permuted)
__global__ __launch_bounds__(256) void prep_w(const float* __restrict__ w1,
                                              const float* __restrict__ pw) {
    const int i = blockIdx.x * 256 + threadIdx.x;
    if (i < 1536 * Cc) {
        g_w1[i] = tf32r(w1[i]);
    } else {
        const int j = i - 1536 * Cc;     // j = kp*512 + c
        const int kp = j >> 9, c = j & 511;
        const int h = kp >> 6, d = kp & 63;
        g_pwt[j] = tf32r(pw[c * 512 + d * 8 + h]);
    }
}

// ---------------- QKV GEMM ----------------
__global__ __launch_bounds__(256, 2) void k_qkv(const float* __restrict__ qkvb) {
    extern __shared__ float dynsm[];
    const int b = blockIdx.z, m0 = blockIdx.y * 128, n0 = blockIdx.x * 128;
    float acc[4][4][4] = {};
    G128::run(dynsm, g_w1 + (size_t)m0 * Cc, Cc,
              g_xn + (size_t)b * Cc * Ss + n0, Ss, Cc, acc);

    const int t = threadIdx.x, w = t >> 5, lane = t & 31;
    const int g = lane >> 2, tg = lane & 3;
    const int wm0 = (w >> 2) * 64, wn0 = (w & 3) * 32;
    #pragma unroll
    for (int mt = 0; mt < 4; mt++) {
        #pragma unroll
        for (int half = 0; half < 2; half++) {
            const int ch = m0 + wm0 + mt * 16 + g + half * 8;
            const float bias = qkvb[ch];
            #pragma unroll
            for (int nt = 0; nt < 4; nt++) {
                const int s = n0 + wn0 + nt * 8 + 2 * tg;
                const float v0 = tf32r(acc[mt][nt][half * 2 + 0] + bias);
                const float v1 = tf32r(acc[mt][nt][half * 2 + 1] + bias);
                if (ch < 512) {            // Q -> qt[b][h][s][d]
                    const int h = ch >> 6, d = ch & 63;
                    float* dst = g_qt + (((size_t)b * 8 + h) * Ss + s) * 64 + d;
                    dst[0] = v0; dst[64] = v1;
                } else if (ch < 1024) {    // K -> k[b][h][d][s]
                    float* dst = g_k + ((size_t)b * 512 + (ch - 512)) * Ss + s;
                    dst[0] = v0; dst[1] = v1;
                } else {                   // V -> vt[b][h][j][d]
                    const int c2 = ch - 1024, h = c2 >> 6, d = c2 & 63;
                    float* dst = g_vt + (((size_t)b * 8 + h) * Ss + s) * 64 + d;
                    dst[0] = v0; dst[64] = v1;
                }
            }
        }
    }
}

// ---------------- fused flash attention ----------------
// 128 threads / 4 warps; warp w owns i-rows [32w, 32w+32) as two 16-row subtiles.
// K/V b-fragments are shared across both subtiles (2 mmas per b-frag load).
// Smem: Ps [2][128][36] (Q staging then P bounce), Ks/Vs double-buffered [2][2][32][72].
__global__ __launch_bounds__(128, 2) void k_attn() {
    extern __shared__ float sm[];
    float* Ps = sm;            // 9216 floats
    float* Ks = sm + 9216;     // 2 bufs x 4608
    float* Vs = sm + 18432;    // 2 bufs x 4608
    const int bh = blockIdx.y, i0 = blockIdx.x * 128;
    const int b = bh >> 3, h = bh & 7;
    const int t = threadIdx.x, w = t >> 5, lane = t & 31;
    const int g = lane >> 2, tg = lane & 3;
    const int wr = w * 32;

    // stage Q tile -> Ps (A layout, chunked k32, pad 36)
    #pragma unroll
    for (int i = 0; i < 16; i++) {
        const int id = t + 128 * i;
        const int row = id >> 4, col = (id & 15) * 4;
        CP_ASYNC16(smem_u32(Ps + (col >> 5) * 4608 + row * 36 + (col & 31)),
                   g_qt + ((size_t)bh * Ss + i0 + row) * 64 + col);
    }
    CP_COMMIT();

    auto issue_kv = [&](int jt, int buf) {
        #pragma unroll
        for (int i = 0; i < 8; i++) {
            const int id = t + 128 * i;
            const int row = id >> 4, c4 = (id & 15) * 4;
            const uint32_t doff = buf * 4608 + (row >> 5) * 2304 + (row & 31) * 72 + c4;
            CP_ASYNC16(smem_u32(Ks + doff),
                       g_k + ((size_t)bh * 64 + row) * Ss + jt * 64 + c4);
            CP_ASYNC16(smem_u32(Vs + doff),
                       g_vt + ((size_t)bh * Ss + jt * 64 + row) * 64 + c4);
        }
    };
    issue_kv(0, 0);
    CP_COMMIT();

    CP_WAIT(1);          // Q staged
    __syncthreads();
    uint32_t qf[2][8][4];
    #pragma unroll
    for (int mt = 0; mt < 2; mt++)
        #pragma unroll
        for (int kf = 0; kf < 8; kf++) {
            const uint32_t* qp = (const uint32_t*)(Ps + (kf >> 2) * 4608
                                 + (wr + 16 * mt + g) * 36 + (kf & 3) * 8 + tg);
            qf[mt][kf][0] = qp[0]; qf[mt][kf][1] = qp[8 * 36];
            qf[mt][kf][2] = qp[4]; qf[mt][kf][3] = qp[8 * 36 + 4];
        }

    float o[2][8][4] = {};
    float mx[4] = {-1e30f, -1e30f, -1e30f, -1e30f};
    float lx[4] = {};

    for (int jt = 0; jt < 16; jt++) {
        const int buf = jt & 1;
        if (jt + 1 < 16) { issue_kv(jt + 1, buf ^ 1); CP_COMMIT(); CP_WAIT(1); }
        else             { CP_WAIT(0); }
        __syncthreads();   // K/V[buf] landed

        // ---- S = Q @ K^T (warp tile 32 x 64, b-frags shared) ----
        float s0[8][4] = {}, s1[8][4] = {};
        const float* Kb = Ks + buf * 4608;
        #pragma unroll
        for (int kf = 0; kf < 8; kf++) {
            const uint32_t* bb = (const uint32_t*)(Kb + (kf >> 2) * 2304 + ((kf & 3) * 8 + tg) * 72 + g);
            #pragma unroll
            for (int nt = 0; nt < 8; nt++) {
                uint32_t bfr[2] = { bb[nt * 8], bb[4 * 72 + nt * 8] };
                mma8(s0[nt], qf[0][kf], bfr);
                mma8(s1[nt], qf[1][kf], bfr);
            }
        }

        // ---- online softmax for 4 row-groups ----
        float tm[4] = {-1e30f, -1e30f, -1e30f, -1e30f};
        #pragma unroll
        for (int nt = 0; nt < 8; nt++) {
            #pragma unroll
            for (int q = 0; q < 4; q++) { s0[nt][q] *= 0.125f; s1[nt][q] *= 0.125f; }
            tm[0] = fmaxf(tm[0], fmaxf(s0[nt][0], s0[nt][1]));
            tm[1] = fmaxf(tm[1], fmaxf(s0[nt][2], s0[nt][3]));
            tm[2] = fmaxf(tm[2], fmaxf(s1[nt][0], s1[nt][1]));
            tm[3] = fmaxf(tm[3], fmaxf(s1[nt][2], s1[nt][3]));
        }
        float al[4];
        #pragma unroll
        for (int q = 0; q < 4; q++) {
            tm[q] = fmaxf(tm[q], __shfl_xor_sync(0xffffffffu, tm[q], 1));
            tm[q] = fmaxf(tm[q], __shfl_xor_sync(0xffffffffu, tm[q], 2));
            const float nm = fmaxf(mx[q], tm[q]);
            al[q] = __expf(mx[q] - nm);
            mx[q] = nm;
        }
        float ps[4] = {};
        #pragma unroll
        for (int nt = 0; nt < 8; nt++) {
            float p0 = __expf(s0[nt][0] - mx[0]), p1 = __expf(s0[nt][1] - mx[0]);
            float p2 = __expf(s0[nt][2] - mx[1]), p3 = __expf(s0[nt][3] - mx[1]);
            float p4 = __expf(s1[nt][0] - mx[2]), p5 = __expf(s1[nt][1] - mx[2]);
            float p6 = __expf(s1[nt][2] - mx[3]), p7 = __expf(s1[nt][3] - mx[3]);
            ps[0] += p0 + p1; ps[1] += p2 + p3; ps[2] += p4 + p5; ps[3] += p6 + p7;
            s0[nt][0] = tf32r(p0); s0[nt][1] = tf32r(p1);
            s0[nt][2] = tf32r(p2); s0[nt][3] = tf32r(p3);
            s1[nt][0] = tf32r(p4); s1[nt][1] = tf32r(p5);
            s1[nt][2] = tf32r(p6); s1[nt][3] = tf32r(p7);
        }
        #pragma unroll
        for (int q = 0; q < 4; q++) {
            ps[q] += __shfl_xor_sync(0xffffffffu, ps[q], 1);
            ps[q] += __shfl_xor_sync(0xffffffffu, ps[q], 2);
            lx[q] = lx[q] * al[q] + ps[q];
        }
        #pragma unroll
        for (int nf = 0; nf < 8; nf++) {
            o[0][nf][0] *= al[0]; o[0][nf][1] *= al[0];
            o[0][nf][2] *= al[1]; o[0][nf][3] *= al[1];
            o[1][nf][0] *= al[2]; o[1][nf][1] *= al[2];
            o[1][nf][2] *= al[3]; o[1][nf][3] *= al[3];
        }

        // ---- bounce P through smem into A layout (warp-private rows) ----
        #pragma unroll
        for (int nt = 0; nt < 8; nt++) {
            float* pp = Ps + (nt >> 2) * 4608 + (wr + g) * 36 + (nt & 3) * 8 + 2 * tg;
            *(float2*)pp             = make_float2(s0[nt][0], s0[nt][1]);
            *(float2*)(pp + 8 * 36)  = make_float2(s0[nt][2], s0[nt][3]);
            *(float2*)(pp + 16 * 36) = make_float2(s1[nt][0], s1[nt][1]);
            *(float2*)(pp + 24 * 36) = make_float2(s1[nt][2], s1[nt][3]);
        }
        __syncwarp();   // intra-warp fragment exchange only

        // ---- O += P @ V (b-frags shared across both subtiles) ----
        const float* Vb = Vs + buf * 4608;
        #pragma unroll
        for (int kf = 0; kf < 8; kf++) {
            const uint32_t* ap = (const uint32_t*)(Ps + (kf >> 2) * 4608 + (wr + g) * 36 + (kf & 3) * 8 + tg);
            uint32_t a0[4] = { ap[0],       ap[8 * 36],      ap[4],           ap[8 * 36 + 4] };
            uint32_t a1[4] = { ap[16 * 36], ap[24 * 36],     ap[16 * 36 + 4], ap[24 * 36 + 4] };
            const uint32_t* bb = (const uint32_t*)(Vb + (kf >> 2) * 2304 + ((kf & 3) * 8 + tg) * 72 + g);
            #pragma unroll
            for (int nf = 0; nf < 8; nf++) {
                uint32_t bfr[2] = { bb[nf * 8], bb[4 * 72 + nf * 8] };
                mma8(o[0][nf], a0, bfr);
                mma8(o[1][nf], a1, bfr);
            }
        }

        __syncthreads();   // WAR guard: all warps done with Ks/Vs[buf]
    }

    // ---- epilogue: O /= l, write ao[b][i][h*64+d] ----
    const float inv[4] = {1.0f / lx[0], 1.0f / lx[1], 1.0f / lx[2], 1.0f / lx[3]};
    float* dst = g_ao + ((size_t)b * Ss + i0 + wr + g) * Cc + h * 64 + 2 * tg;
    #pragma unroll
    for (int nf = 0; nf < 8; nf++) {
        *(float2*)(dst + nf * 8) =
            make_float2(tf32r(o[0][nf][0] * inv[0]), tf32r(o[0][nf][1] * inv[0]));
        *(float2*)(dst + 8 * Cc + nf * 8) =
            make_float2(tf32r(o[0][nf][2] * inv[1]), tf32r(o[0][nf][3] * inv[1]));
        *(float2*)(dst + 16 * Cc + nf * 8) =
            make_float2(tf32r(o[1][nf][0] * inv[2]), tf32r(o[1][nf][1] * inv[2]));
        *(float2*)(dst + 24 * Cc + nf * 8) =
            make_float2(tf32r(o[1][nf][2] * inv[3]), tf32r(o[1][nf][3] * inv[3]));
    }
}

// ---------------- proj GEMM ----------------
__global__ __launch_bounds__(256, 2) void k_proj(const float* __restrict__ projb) {
    extern __shared__ float dynsm[];
    const int b = blockIdx.z, m0 = blockIdx.y * 128, n0 = blockIdx.x * 128;
    float acc[4][4][4] = {};
    G128::run(dynsm, g_ao + ((size_t)b * Ss + m0) * Cc, Cc,
              g_pwt + n0, Cc, Cc, acc);

    const int t = threadIdx.x, w = t >> 5, lane = t & 31;
    const int g = lane >> 2, tg = lane & 3;
    const int wm0 = (w >> 2) * 64, wn0 = (w & 3) * 32;
    #pragma unroll
    for (int mt = 0; mt < 4; mt++)
        #pragma unroll
        for (int half = 0; half < 2; half++) {
            const int s = m0 + wm0 + mt * 16 + g + half * 8;
            #pragma unroll
            for (int nt = 0; nt < 4; nt++) {
                const int c = n0 + wn0 + nt * 8 + 2 * tg;
                float2 v = make_float2(acc[mt][nt][half * 2] + projb[c],
                                       acc[mt][nt][half * 2 + 1] + projb[c + 1]);
                *(float2*)(g_y + ((size_t)b * Ss + s) * Cc + c) = v;
            }
        }
}

// out[b][c][s] = gn(y[b][s][c]) + x[b][c][s]
__global__ __launch_bounds__(256) void final_kernel(
    const float* __restrict__ x, const float* __restrict__ ow,
    const float* __restrict__ ob, float* __restrict__ out)
{
    __shared__ float tl[32][33];
    const int b = blockIdx.z;
    const int s0 = blockIdx.x * 32, c0 = blockIdx.y * 32;
    const int tx = threadIdx.x, ty = threadIdx.y;
    const float mean = g_stats[16 + b], rstd = g_stats[24 + b];
    #pragma unroll
    for (int k = 0; k < 4; k++)
        tl[ty + 8 * k][tx] = g_y[((size_t)b * Ss + s0 + ty + 8 * k) * Cc + c0 + tx];
    __syncthreads();
    #pragma unroll
    for (int k = 0; k < 4; k++) {
        const int c = c0 + ty + 8 * k;
        const float sc = rstd * ow[c], sv = ob[c] - mean * sc;
        const size_t o = ((size_t)b * Cc + c) * Ss + s0 + tx;
        out[o] = fmaf(tl[tx][ty + 8 * k], sc, sv) + x[o];
    }
}

// ---------------- launch ----------------
extern "C" void kernel_launch(void* const* d_in, const int* in_sizes, int n_in,
                              void* d_out, int out_size) {
    (void)in_sizes; (void)n_in; (void)out_size;
    const float* x      = (const float*)d_in[0];
    const float* norm_w = (const float*)d_in[1];
    const float* norm_b = (const float*)d_in[2];
    const float* qkv_w  = (const float*)d_in[3];
    const float* qkv_b  = (const float*)d_in[4];
    const float* proj_w = (const float*)d_in[5];
    const float* proj_b = (const float*)d_in[6];
    const float* onw    = (const float*)d_in[7];
    const float* onb    = (const float*)d_in[8];
    float* out = (float*)d_out;

    const int SM128   = G128::SMEM_BYTES;      // 71680
    const int SM_ATTN = 27648 * 4;              // 110592
    cudaFuncSetAttribute(k_qkv,  cudaFuncAttributeMaxDynamicSharedMemorySize, SM128);
    cudaFuncSetAttribute(k_attn, cudaFuncAttributeMaxDynamicSharedMemorySize, SM_ATTN);
    cudaFuncSetAttribute(k_proj, cudaFuncAttributeMaxDynamicSharedMemorySize, SM128);

    float* yp = nullptr;
    cudaGetSymbolAddress((void**)&yp, g_y);

    stats_kernel<<<Bn, 256>>>(x, 0);
    norm_x<<<(Bn * Cc * Ss / 4) / 256, 256>>>(x, norm_w, norm_b);
    prep_w<<<(1536 * Cc + Cc * Cc) / 256, 256>>>(qkv_w, proj_w);

    k_qkv <<<dim3(8, 12, Bn), 256, SM128>>>(qkv_b);
    k_attn<<<dim3(8, 64), 128, SM_ATTN>>>();
    k_proj<<<dim3(4, 8, Bn), 256, SM128>>>(proj_b);

    stats_kernel<<<Bn, 256>>>(yp, 16);
    final_kernel<<<dim3(32, 16, Bn), dim3(32, 8)>>>(x, onw, onb, out);
}

// round 7
// speedup vs baseline: 3.0999x; 1.0007x over previous
#include <cuda_runtime.h>
#include <cstdint>

#define Bn  8
#define Cc  512
#define Ss  1024
#define NHh 8
#define HDd 64
#define EPSn 1e-5f

// ---------------- scratch ----------------
__device__ float g_xn [(size_t)Bn * Cc * Ss];          // normalized+rounded x [b][c][s]
__device__ float g_w1 [(size_t)1536 * Cc];             // rounded qkv_w [ch][c]
__device__ float g_pwt[(size_t)Cc * Cc];               // rounded proj_w^T permuted: [k'=h*64+d][c]
__device__ float g_qt [(size_t)Bn * NHh * Ss * HDd];   // Q^T [b][h][s][d]
__device__ float g_k  [(size_t)Bn * NHh * HDd * Ss];   // K   [b][h][d][s]
__device__ float g_vt [(size_t)Bn * NHh * Ss * HDd];   // V^T [b][h][j][d]
__device__ float g_ao [(size_t)Bn * Ss * Cc];          // attn-out [b][s][k'=h*64+d]
__device__ float g_y  [(size_t)Bn * Ss * Cc];          // proj out [b][s][c]
__device__ float g_stats[32];

// ---------------- helpers ----------------
__device__ __forceinline__ uint32_t smem_u32(const void* p) {
    uint32_t a;
    asm("{ .reg .u64 t; cvta.to.shared.u64 t, %1; cvt.u32.u64 %0, t; }" : "=r"(a) : "l"(p));
    return a;
}
__device__ __forceinline__ float tf32r(float x) {
    uint32_t o;
    asm("cvt.rn.tf32.f32 %0, %1;" : "=r"(o) : "f"(x));
    return __uint_as_float(o);
}
#define CP_ASYNC16(dst, src) \
    asm volatile("cp.async.cg.shared.global [%0], [%1], 16;" :: "r"(dst), "l"(src))
#define CP_COMMIT() asm volatile("cp.async.commit_group;" ::: "memory")
#define CP_WAIT(n)  asm volatile("cp.async.wait_group %0;" :: "n"(n) : "memory")

__device__ __forceinline__ void mma8(float* c, const uint32_t* a, const uint32_t* b) {
    asm volatile(
        "mma.sync.aligned.m16n8k8.row.col.f32.tf32.tf32.f32 "
        "{%0,%1,%2,%3}, {%4,%5,%6,%7}, {%8,%9}, {%0,%1,%2,%3};"
        : "+f"(c[0]), "+f"(c[1]), "+f"(c[2]), "+f"(c[3])
        : "r"(a[0]), "r"(a[1]), "r"(a[2]), "r"(a[3]), "r"(b[0]), "r"(b[1]));
}

// ---------------- shared GEMM core (dense GEMMs) ----------------
// Single-barrier pipelined mainloop: wait -> sync -> issue next -> compute.
template<int BN, int WR, int WC>
struct Gemm {
    static constexpr int TM = 128 / WR / 16;
    static constexpr int TN = BN / WC / 8;
    static constexpr int BP = BN + 8;
    static constexpr int ASZ = 128 * 36;
    static constexpr int BSZ = 32 * BP;
    static constexpr int NB4 = BN / 32;
    static constexpr int SMEM_BYTES = 2 * (ASZ + BSZ) * 4;

    __device__ static void issue(float* As, float* Bs,
                                 const float* __restrict__ A, int lda,
                                 const float* __restrict__ B, int ldb,
                                 int k0, int t) {
        #pragma unroll
        for (int i = 0; i < 4; i++) {
            const int id = t + 256 * i;
            const int row = id >> 3, c4 = id & 7;
            CP_ASYNC16(smem_u32(As + row * 36 + c4 * 4),
                       A + (size_t)row * lda + k0 + c4 * 4);
        }
        #pragma unroll
        for (int i = 0; i < NB4; i++) {
            const int id = t + 256 * i;
            const int row = id / (BN / 4), c4 = id % (BN / 4);
            CP_ASYNC16(smem_u32(Bs + row * BP + c4 * 4),
                       B + (size_t)(k0 + row) * ldb + c4 * 4);
        }
    }

    __device__ static void compute(const float* As, const float* Bs,
                                   float (&acc)[TM][TN][4]) {
        const int t = threadIdx.x, w = t >> 5, lane = t & 31;
        const int g = lane >> 2, tg = lane & 3;
        const int wm0 = (w / WC) * (128 / WR);
        const int wn0 = (w % WC) * (BN / WC);
        const uint32_t* Au = (const uint32_t*)As;
        const uint32_t* Bu = (const uint32_t*)Bs;
        #pragma unroll
        for (int kk = 0; kk < 4; kk++) {
            const int k8 = kk * 8;
            uint32_t a[TM][4], b[TN][2];
            #pragma unroll
            for (int mt = 0; mt < TM; mt++) {
                const uint32_t* ap = Au + (wm0 + mt * 16 + g) * 36 + k8 + tg;
                a[mt][0] = ap[0];
                a[mt][1] = ap[8 * 36];
                a[mt][2] = ap[4];
                a[mt][3] = ap[8 * 36 + 4];
            }
            #pragma unroll
            for (int nt = 0; nt < TN; nt++) {
                const uint32_t* bp = Bu + (k8 + tg) * BP + wn0 + nt * 8 + g;
                b[nt][0] = bp[0];
                b[nt][1] = bp[4 * BP];
            }
            #pragma unroll
            for (int mt = 0; mt < TM; mt++)
                #pragma unroll
                for (int nt = 0; nt < TN; nt++)
                    mma8(acc[mt][nt], a[mt], b[nt]);
        }
    }

    __device__ static void run(float* sm,
                               const float* __restrict__ A, int lda,
                               const float* __restrict__ B, int ldb,
                               int ktot, float (&acc)[TM][TN][4]) {
        float* As0 = sm;
        float* Bs0 = As0 + ASZ;
        float* As1 = Bs0 + BSZ;
        float* Bs1 = As1 + ASZ;
        const int t = threadIdx.x;
        const int NCH = ktot / 32;

        issue(As0, Bs0, A, lda, B, ldb, 0, t);
        CP_COMMIT();
        for (int c = 0; c < NCH; c++) {
            const int buf = c & 1;
            CP_WAIT(0);          // chunk c landed
            __syncthreads();     // visible to all; all warps done computing c-1
            if (c + 1 < NCH) {   // stage buf^1 fully consumed at iter c-1 -> safe
                issue(buf ? As0 : As1, buf ? Bs0 : Bs1, A, lda, B, ldb, (c + 1) * 32, t);
                CP_COMMIT();
            }
            compute(buf ? As1 : As0, buf ? Bs1 : Bs0, acc);
        }
    }
};

using G128 = Gemm<128, 2, 4>;

// ---------------- prep kernels ----------------
__global__ __launch_bounds__(256) void stats_kernel(const float* __restrict__ src, int off) {
    const int b = blockIdx.x;
    const float4* p = (const float4*)(src + (size_t)b * Cc * Ss);
    const int n4 = Cc * Ss / 4;
    float s = 0.f, s2 = 0.f;
    for (int i = threadIdx.x; i < n4; i += 256) {
        float4 v = p[i];
        s += (v.x + v.y) + (v.z + v.w);
        s2 = fmaf(v.x, v.x, fmaf(v.y, v.y, fmaf(v.z, v.z, fmaf(v.w, v.w, s2))));
    }
    __shared__ float sh[256], sh2[256];
    sh[threadIdx.x] = s; sh2[threadIdx.x] = s2;
    __syncthreads();
    for (int st = 128; st > 0; st >>= 1) {
        if (threadIdx.x < st) { sh[threadIdx.x] += sh[threadIdx.x + st]; sh2[threadIdx.x] += sh2[threadIdx.x + st]; }
        __syncthreads();
    }
    if (threadIdx.x == 0) {
        const float N = (float)(Cc * Ss);
        float mean = sh[0] / N;
        float var  = sh2[0] / N - mean * mean;
        g_stats[off + b] = mean;
        g_stats[off + 8 + b] = rsqrtf(var + EPSn);
    }
}

__global__ __launch_bounds__(256) void norm_x(const float* __restrict__ x,
                                              const float* __restrict__ nw,
                                              const float* __restrict__ nb) {
    const int i4 = blockIdx.x * 256 + threadIdx.x;
    const int per_b = Cc * Ss / 4;
    const int b = i4 / per_b;
    const int r = i4 - b * per_b;
    const int c = r >> 8;
    const float mean = g_stats[b], rstd = g_stats[8 + b];
    const float sc = rstd * nw[c], sv = nb[c] - mean * sc;
    float4 v = ((const float4*)x)[i4];
    v.x = tf32r(fmaf(v.x, sc, sv));
    v.y = tf32r(fmaf(v.y, sc, sv));
    v.z = tf32r(fmaf(v.z, sc, sv));
    v.w = tf32r(fmaf(v.w, sc, sv));
    ((float4*)g_xn)[i4] = v;
}

// merged weight prep: [0, 1536*512) -> g_w1, rest -> g_pwt (permuted)
__global__ __launch_bounds__(256) void prep_w(const float* __restrict__ w1,
                                              const float* __restrict__ pw) {
    const int i = blockIdx.x * 256 + threadIdx.x;
    if (i < 1536 * Cc) {
        g_w1[i] = tf32r(w1[i]);
    } else {
        const int j = i - 1536 * Cc;     // j = kp*512 + c
        const int kp = j >> 9, c = j & 511;
        const int h = kp >> 6, d = kp & 63;
        g_pwt[j] = tf32r(pw[c * 512 + d * 8 + h]);
    }
}

// ---------------- QKV GEMM ----------------
__global__ __launch_bounds__(256, 2) void k_qkv(const float* __restrict__ qkvb) {
    extern __shared__ float dynsm[];
    const int b = blockIdx.z, m0 = blockIdx.y * 128, n0 = blockIdx.x * 128;
    float acc[4][4][4] = {};
    G128::run(dynsm, g_w1 + (size_t)m0 * Cc, Cc,
              g_xn + (size_t)b * Cc * Ss + n0, Ss, Cc, acc);

    const int t = threadIdx.x, w = t >> 5, lane = t & 31;
    const int g = lane >> 2, tg = lane & 3;
    const int wm0 = (w >> 2) * 64, wn0 = (w & 3) * 32;
    #pragma unroll
    for (int mt = 0; mt < 4; mt++) {
        #pragma unroll
        for (int half = 0; half < 2; half++) {
            const int ch = m0 + wm0 + mt * 16 + g + half * 8;
            const float bias = qkvb[ch];
            #pragma unroll
            for (int nt = 0; nt < 4; nt++) {
                const int s = n0 + wn0 + nt * 8 + 2 * tg;
                const float v0 = tf32r(acc[mt][nt][half * 2 + 0] + bias);
                const float v1 = tf32r(acc[mt][nt][half * 2 + 1] + bias);
                if (ch < 512) {            // Q -> qt[b][h][s][d]
                    const int h = ch >> 6, d = ch & 63;
                    float* dst = g_qt + (((size_t)b * 8 + h) * Ss + s) * 64 + d;
                    dst[0] = v0; dst[64] = v1;
                } else if (ch < 1024) {    // K -> k[b][h][d][s]
                    float* dst = g_k + ((size_t)b * 512 + (ch - 512)) * Ss + s;
                    dst[0] = v0; dst[1] = v1;
                } else {                   // V -> vt[b][h][j][d]
                    const int c2 = ch - 1024, h = c2 >> 6, d = c2 & 63;
                    float* dst = g_vt + (((size_t)b * 8 + h) * Ss + s) * 64 + d;
                    dst[0] = v0; dst[64] = v1;
                }
            }
        }
    }
}

// ---------------- fused flash attention ----------------
// 128 threads / 4 warps; warp w owns i-rows [32w, 32w+32) as two 16-row subtiles.
// Single-barrier pipelined K/V loop: wait -> sync -> issue next -> compute.
// Smem: Ps [2][128][36] (Q staging then P bounce), Ks/Vs double-buffered [2][2][32][72].
__global__ __launch_bounds__(128, 2) void k_attn() {
    extern __shared__ float sm[];
    float* Ps = sm;            // 9216 floats
    float* Ks = sm + 9216;     // 2 bufs x 4608
    float* Vs = sm + 18432;    // 2 bufs x 4608
    const int bh = blockIdx.y, i0 = blockIdx.x * 128;
    const int b = bh >> 3, h = bh & 7;
    const int t = threadIdx.x, w = t >> 5, lane = t & 31;
    const int g = lane >> 2, tg = lane & 3;
    const int wr = w * 32;

    // stage Q tile -> Ps (A layout, chunked k32, pad 36)
    #pragma unroll
    for (int i = 0; i < 16; i++) {
        const int id = t + 128 * i;
        const int row = id >> 4, col = (id & 15) * 4;
        CP_ASYNC16(smem_u32(Ps + (col >> 5) * 4608 + row * 36 + (col & 31)),
                   g_qt + ((size_t)bh * Ss + i0 + row) * 64 + col);
    }
    CP_COMMIT();

    auto issue_kv = [&](int jt, int buf) {
        #pragma unroll
        for (int i = 0; i < 8; i++) {
            const int id = t + 128 * i;
            const int row = id >> 4, c4 = (id & 15) * 4;
            const uint32_t doff = buf * 4608 + (row >> 5) * 2304 + (row & 31) * 72 + c4;
            CP_ASYNC16(smem_u32(Ks + doff),
                       g_k + ((size_t)bh * 64 + row) * Ss + jt * 64 + c4);
            CP_ASYNC16(smem_u32(Vs + doff),
                       g_vt + ((size_t)bh * Ss + jt * 64 + row) * 64 + c4);
        }
    };
    issue_kv(0, 0);
    CP_COMMIT();

    CP_WAIT(1);          // Q staged (kv0 may still be in flight)
    __syncthreads();
    uint32_t qf[2][8][4];
    #pragma unroll
    for (int mt = 0; mt < 2; mt++)
        #pragma unroll
        for (int kf = 0; kf < 8; kf++) {
            const uint32_t* qp = (const uint32_t*)(Ps + (kf >> 2) * 4608
                                 + (wr + 16 * mt + g) * 36 + (kf & 3) * 8 + tg);
            qf[mt][kf][0] = qp[0]; qf[mt][kf][1] = qp[8 * 36];
            qf[mt][kf][2] = qp[4]; qf[mt][kf][3] = qp[8 * 36 + 4];
        }

    float o[2][8][4] = {};
    float mx[4] = {-1e30f, -1e30f, -1e30f, -1e30f};
    float lx[4] = {};

    for (int jt = 0; jt < 16; jt++) {
        const int buf = jt & 1;
        CP_WAIT(0);          // K/V chunk jt landed
        __syncthreads();     // visible; all warps done with buf^1 (PV of jt-1)
        if (jt + 1 < 16) {   // safe to overwrite buf^1 now
            issue_kv(jt + 1, buf ^ 1);
            CP_COMMIT();
        }

        // ---- S = Q @ K^T (warp tile 32 x 64, b-frags shared) ----
        float s0[8][4] = {}, s1[8][4] = {};
        const float* Kb = Ks + buf * 4608;
        #pragma unroll
        for (int kf = 0; kf < 8; kf++) {
            const uint32_t* bb = (const uint32_t*)(Kb + (kf >> 2) * 2304 + ((kf & 3) * 8 + tg) * 72 + g);
            #pragma unroll
            for (int nt = 0; nt < 8; nt++) {
                uint32_t bfr[2] = { bb[nt * 8], bb[4 * 72 + nt * 8] };
                mma8(s0[nt], qf[0][kf], bfr);
                mma8(s1[nt], qf[1][kf], bfr);
            }
        }

        // ---- online softmax for 4 row-groups ----
        float tm[4] = {-1e30f, -1e30f, -1e30f, -1e30f};
        #pragma unroll
        for (int nt = 0; nt < 8; nt++) {
            #pragma unroll
            for (int q = 0; q < 4; q++) { s0[nt][q] *= 0.125f; s1[nt][q] *= 0.125f; }
            tm[0] = fmaxf(tm[0], fmaxf(s0[nt][0], s0[nt][1]));
            tm[1] = fmaxf(tm[1], fmaxf(s0[nt][2], s0[nt][3]));
            tm[2] = fmaxf(tm[2], fmaxf(s1[nt][0], s1[nt][1]));
            tm[3] = fmaxf(tm[3], fmaxf(s1[nt][2], s1[nt][3]));
        }
        float al[4];
        #pragma unroll
        for (int q = 0; q < 4; q++) {
            tm[q] = fmaxf(tm[q], __shfl_xor_sync(0xffffffffu, tm[q], 1));
            tm[q] = fmaxf(tm[q], __shfl_xor_sync(0xffffffffu, tm[q], 2));
            const float nm = fmaxf(mx[q], tm[q]);
            al[q] = __expf(mx[q] - nm);
            mx[q] = nm;
        }
        float ps[4] = {};
        #pragma unroll
        for (int nt = 0; nt < 8; nt++) {
            float p0 = __expf(s0[nt][0] - mx[0]), p1 = __expf(s0[nt][1] - mx[0]);
            float p2 = __expf(s0[nt][2] - mx[1]), p3 = __expf(s0[nt][3] - mx[1]);
            float p4 = __expf(s1[nt][0] - mx[2]), p5 = __expf(s1[nt][1] - mx[2]);
            float p6 = __expf(s1[nt][2] - mx[3]), p7 = __expf(s1[nt][3] - mx[3]);
            ps[0] += p0 + p1; ps[1] += p2 + p3; ps[2] += p4 + p5; ps[3] += p6 + p7;
            s0[nt][0] = tf32r(p0); s0[nt][1] = tf32r(p1);
            s0[nt][2] = tf32r(p2); s0[nt][3] = tf32r(p3);
            s1[nt][0] = tf32r(p4); s1[nt][1] = tf32r(p5);
            s1[nt][2] = tf32r(p6); s1[nt][3] = tf32r(p7);
        }
        #pragma unroll
        for (int q = 0; q < 4; q++) {
            ps[q] += __shfl_xor_sync(0xffffffffu, ps[q], 1);
            ps[q] += __shfl_xor_sync(0xffffffffu, ps[q], 2);
            lx[q] = lx[q] * al[q] + ps[q];
        }
        #pragma unroll
        for (int nf = 0; nf < 8; nf++) {
            o[0][nf][0] *= al[0]; o[0][nf][1] *= al[0];
            o[0][nf][2] *= al[1]; o[0][nf][3] *= al[1];
            o[1][nf][0] *= al[2]; o[1][nf][1] *= al[2];
            o[1][nf][2] *= al[3]; o[1][nf][3] *= al[3];
        }

        // ---- bounce P through smem into A layout (warp-private rows) ----
        #pragma unroll
        for (int nt = 0; nt < 8; nt++) {
            float* pp = Ps + (nt >> 2) * 4608 + (wr + g) * 36 + (nt & 3) * 8 + 2 * tg;
            *(float2*)pp             = make_float2(s0[nt][0], s0[nt][1]);
            *(float2*)(pp + 8 * 36)  = make_float2(s0[nt][2], s0[nt][3]);
            *(float2*)(pp + 16 * 36) = make_float2(s1[nt][0], s1[nt][1]);
            *(float2*)(pp + 24 * 36) = make_float2(s1[nt][2], s1[nt][3]);
        }
        __syncwarp();   // intra-warp fragment exchange only

        // ---- O += P @ V (b-frags shared across both subtiles) ----
        const float* Vb = Vs + buf * 4608;
        #pragma unroll
        for (int kf = 0; kf < 8; kf++) {
            const uint32_t* ap = (const uint32_t*)(Ps + (kf >> 2) * 4608 + (wr + g) * 36 + (kf & 3) * 8 + tg);
            uint32_t a0[4] = { ap[0],       ap[8 * 36],      ap[4],           ap[8 * 36 + 4] };
            uint32_t a1[4] = { ap[16 * 36], ap[24 * 36],     ap[16 * 36 + 4], ap[24 * 36 + 4] };
            const uint32_t* bb = (const uint32_t*)(Vb + (kf >> 2) * 2304 + ((kf & 3) * 8 + tg) * 72 + g);
            #pragma unroll
            for (int nf = 0; nf < 8; nf++) {
                uint32_t bfr[2] = { bb[nf * 8], bb[4 * 72 + nf * 8] };
                mma8(o[0][nf], a0, bfr);
                mma8(o[1][nf], a1, bfr);
            }
        }
        // no trailing barrier: next iteration's top barrier is the WAR guard
    }

    // ---- epilogue: O /= l, write ao[b][i][h*64+d] ----
    const float inv[4] = {1.0f / lx[0], 1.0f / lx[1], 1.0f / lx[2], 1.0f / lx[3]};
    float* dst = g_ao + ((size_t)b * Ss + i0 + wr + g) * Cc + h * 64 + 2 * tg;
    #pragma unroll
    for (int nf = 0; nf < 8; nf++) {
        *(float2*)(dst + nf * 8) =
            make_float2(tf32r(o[0][nf][0] * inv[0]), tf32r(o[0][nf][1] * inv[0]));
        *(float2*)(dst + 8 * Cc + nf * 8) =
            make_float2(tf32r(o[0][nf][2] * inv[1]), tf32r(o[0][nf][3] * inv[1]));
        *(float2*)(dst + 16 * Cc + nf * 8) =
            make_float2(tf32r(o[1][nf][0] * inv[2]), tf32r(o[1][nf][1] * inv[2]));
        *(float2*)(dst + 24 * Cc + nf * 8) =
            make_float2(tf32r(o[1][nf][2] * inv[3]), tf32r(o[1][nf][3] * inv[3]));
    }
}

// ---------------- proj GEMM ----------------
__global__ __launch_bounds__(256, 2) void k_proj(const float* __restrict__ projb) {
    extern __shared__ float dynsm[];
    const int b = blockIdx.z, m0 = blockIdx.y * 128, n0 = blockIdx.x * 128;
    float acc[4][4][4] = {};
    G128::run(dynsm, g_ao + ((size_t)b * Ss + m0) * Cc, Cc,
              g_pwt + n0, Cc, Cc, acc);

    const int t = threadIdx.x, w = t >> 5, lane = t & 31;
    const int g = lane >> 2, tg = lane & 3;
    const int wm0 = (w >> 2) * 64, wn0 = (w & 3) * 32;
    #pragma unroll
    for (int mt = 0; mt < 4; mt++)
        #pragma unroll
        for (int half = 0; half < 2; half++) {
            const int s = m0 + wm0 + mt * 16 + g + half * 8;
            #pragma unroll
            for (int nt = 0; nt < 4; nt++) {
                const int c = n0 + wn0 + nt * 8 + 2 * tg;
                float2 v = make_float2(acc[mt][nt][half * 2] + projb[c],
                                       acc[mt][nt][half * 2 + 1] + projb[c + 1]);
                *(float2*)(g_y + ((size_t)b * Ss + s) * Cc + c) = v;
            }
        }
}

// out[b][c][s] = gn(y[b][s][c]) + x[b][c][s]
__global__ __launch_bounds__(256) void final_kernel(
    const float* __restrict__ x, const float* __restrict__ ow,
    const float* __restrict__ ob, float* __restrict__ out)
{
    __shared__ float tl[32][33];
    const int b = blockIdx.z;
    const int s0 = blockIdx.x * 32, c0 = blockIdx.y * 32;
    const int tx = threadIdx.x, ty = threadIdx.y;
    const float mean = g_stats[16 + b], rstd = g_stats[24 + b];
    #pragma unroll
    for (int k = 0; k < 4; k++)
        tl[ty + 8 * k][tx] = g_y[((size_t)b * Ss + s0 + ty + 8 * k) * Cc + c0 + tx];
    __syncthreads();
    #pragma unroll
    for (int k = 0; k < 4; k++) {
        const int c = c0 + ty + 8 * k;
        const float sc = rstd * ow[c], sv = ob[c] - mean * sc;
        const size_t o = ((size_t)b * Cc + c) * Ss + s0 + tx;
        out[o] = fmaf(tl[tx][ty + 8 * k], sc, sv) + x[o];
    }
}

// ---------------- launch ----------------
extern "C" void kernel_launch(void* const* d_in, const int* in_sizes, int n_in,
                              void* d_out, int out_size) {
    (void)in_sizes; (void)n_in; (void)out_size;
    const float* x      = (const float*)d_in[0];
    const float* norm_w = (const float*)d_in[1];
    const float* norm_b = (const float*)d_in[2];
    const float* qkv_w  = (const float*)d_in[3];
    const float* qkv_b  = (const float*)d_in[4];
    const float* proj_w = (const float*)d_in[5];
    const float* proj_b = (const float*)d_in[6];
    const float* onw    = (const float*)d_in[7];
    const float* onb    = (const float*)d_in[8];
    float* out = (float*)d_out;

    const int SM128   = G128::SMEM_BYTES;      // 71680
    const int SM_ATTN = 27648 * 4;              // 110592
    cudaFuncSetAttribute(k_qkv,  cudaFuncAttributeMaxDynamicSharedMemorySize, SM128);
    cudaFuncSetAttribute(k_attn, cudaFuncAttributeMaxDynamicSharedMemorySize, SM_ATTN);
    cudaFuncSetAttribute(k_proj, cudaFuncAttributeMaxDynamicSharedMemorySize, SM128);

    float* yp = nullptr;
    cudaGetSymbolAddress((void**)&yp, g_y);

    stats_kernel<<<Bn, 256>>>(x, 0);
    norm_x<<<(Bn * Cc * Ss / 4) / 256, 256>>>(x, norm_w, norm_b);
    prep_w<<<(1536 * Cc + Cc * Cc) / 256, 256>>>(qkv_w, proj_w);

    k_qkv <<<dim3(8, 12, Bn), 256, SM128>>>(qkv_b);
    k_attn<<<dim3(8, 64), 128, SM_ATTN>>>();
    k_proj<<<dim3(4, 8, Bn), 256, SM128>>>(proj_b);

    stats_kernel<<<Bn, 256>>>(yp, 16);
    final_kernel<<<dim3(32, 16, Bn), dim3(32, 8)>>>(x, onw, onb, out);
}